// round 1
// baseline (speedup 1.0000x reference)
#include <cuda_runtime.h>
#include <math.h>

// Problem constants
#define BB 2
#define SS 2048
#define EE 1024
#define HH 8
#define DHH 64
#define DAA 512          // H*DH
#define DMLP 2048        // 4*(E/2)
#define NTOK 4096        // B*S
#define SCALE_ATTN 0.04419417382415922f   // 1/sqrt(512)
#define LN_EPS 1e-5f

// ---------------- scratch (static device allocations; no cudaMalloc allowed) ----
__device__ float g_ln [NTOK * EE];     // LN outputs (reused)
__device__ float g_mid[NTOK * DMLP];   // MLP hidden
__device__ float g_q  [NTOK * EE];     // q = LN(cov)
__device__ float g_qp [NTOK * DAA];
__device__ float g_kp [NTOK * DAA];
__device__ float g_vp [NTOK * DAA];
__device__ float g_ao [NTOK * DAA];    // attention output (token-major)

// ---------------- LayerNorm: one block per row of E=1024 ----------------
__device__ __forceinline__ float block_reduce_sum(float v) {
    __shared__ float red[32];
    int lane = threadIdx.x & 31, w = threadIdx.x >> 5;
#pragma unroll
    for (int o = 16; o > 0; o >>= 1) v += __shfl_xor_sync(0xffffffffu, v, o);
    __syncthreads();
    if (lane == 0) red[w] = v;
    __syncthreads();
    v = (lane < 8) ? red[lane] : 0.f;
#pragma unroll
    for (int o = 16; o > 0; o >>= 1) v += __shfl_xor_sync(0xffffffffu, v, o);
    return v;   // valid in every thread (all warps read red[0..7])
}

__global__ void ln_kernel(const float* __restrict__ x, const float* __restrict__ g,
                          const float* __restrict__ b, float* __restrict__ out) {
    int row = blockIdx.x;
    const float* xr = x + (size_t)row * EE;
    float* orow = out + (size_t)row * EE;
    int tid = threadIdx.x;    // 256 threads, 4 elements each
    float v[4]; float s = 0.f;
#pragma unroll
    for (int i = 0; i < 4; i++) { v[i] = xr[tid + 256 * i]; s += v[i]; }
    float mean = block_reduce_sum(s) * (1.0f / EE);
    float sq = 0.f;
#pragma unroll
    for (int i = 0; i < 4; i++) { float d = v[i] - mean; sq += d * d; }
    float var = block_reduce_sum(sq) * (1.0f / EE);
    float rstd = rsqrtf(var + LN_EPS);
#pragma unroll
    for (int i = 0; i < 4; i++) {
        int c = tid + 256 * i;
        orow[c] = (v[i] - mean) * rstd * g[c] + b[c];
    }
}

// ---------------- SGEMM 128x128x16, 256 threads, 8x8 per thread ----------------
// MODE 0: C = A@B
// MODE 1: C = gelu(A@B + bias)          (exact erf gelu)
// MODE 2: C = A@B + bias + R
// MODE 3: C = A@B + R
template<int MODE>
__global__ void __launch_bounds__(256, 2) gemm_kernel(
    const float* __restrict__ A, const float* __restrict__ Bw,
    const float* __restrict__ bias, const float* __restrict__ R,
    float* __restrict__ C, int M, int N, int K)
{
    __shared__ float As[16][132];   // transposed: As[k][m]
    __shared__ float Bs[16][132];   // Bs[k][n]

    const int tid = threadIdx.x;
    const int tx = tid & 15;        // N direction
    const int ty = tid >> 4;        // M direction
    const int m0 = blockIdx.y * 128;
    const int n0 = blockIdx.x * 128;

    float acc[8][8];
#pragma unroll
    for (int i = 0; i < 8; i++)
#pragma unroll
        for (int j = 0; j < 8; j++) acc[i][j] = 0.f;

    for (int k0 = 0; k0 < K; k0 += 16) {
        // load A tile: 128 rows x 16 cols = 512 float4
#pragma unroll
        for (int i = 0; i < 2; i++) {
            int idx = tid + i * 256;
            int r  = idx >> 2;      // 0..127
            int c4 = idx & 3;       // 0..3
            float4 a = *(const float4*)&A[(size_t)(m0 + r) * K + k0 + c4 * 4];
            As[c4 * 4 + 0][r] = a.x;
            As[c4 * 4 + 1][r] = a.y;
            As[c4 * 4 + 2][r] = a.z;
            As[c4 * 4 + 3][r] = a.w;
        }
        // load B tile: 16 rows x 128 cols = 512 float4
#pragma unroll
        for (int i = 0; i < 2; i++) {
            int idx = tid + i * 256;
            int r  = idx >> 5;      // 0..15
            int c4 = idx & 31;      // 0..31
            *(float4*)&Bs[r][c4 * 4] = *(const float4*)&Bw[(size_t)(k0 + r) * N + n0 + c4 * 4];
        }
        __syncthreads();
#pragma unroll
        for (int kk = 0; kk < 16; kk++) {
            float a[8], b[8];
            *(float4*)&a[0] = *(float4*)&As[kk][ty * 8];
            *(float4*)&a[4] = *(float4*)&As[kk][ty * 8 + 4];
            *(float4*)&b[0] = *(float4*)&Bs[kk][tx * 8];
            *(float4*)&b[4] = *(float4*)&Bs[kk][tx * 8 + 4];
#pragma unroll
            for (int i = 0; i < 8; i++)
#pragma unroll
                for (int j = 0; j < 8; j++)
                    acc[i][j] += a[i] * b[j];
        }
        __syncthreads();
    }

#pragma unroll
    for (int i = 0; i < 8; i++) {
        int row = m0 + ty * 8 + i;
#pragma unroll
        for (int j = 0; j < 8; j++) {
            int col = n0 + tx * 8 + j;
            float v = acc[i][j];
            if (MODE == 1) {
                v += bias[col];
                v = 0.5f * v * (1.0f + erff(v * 0.70710678118654752f));
            } else if (MODE == 2) {
                v += bias[col] + R[(size_t)row * N + col];
            } else if (MODE == 3) {
                v += R[(size_t)row * N + col];
            }
            C[(size_t)row * N + col] = v;
        }
    }
}

// ---------------- RoPE (interleaved pairs), in-place on [NTOK, DA] ----------------
__global__ void rope_kernel(float* __restrict__ x) {
    int idx = blockIdx.x * blockDim.x + threadIdx.x;   // 4096*256 total
    int pc    = idx & 255;          // pair index within token (0..255)
    int token = idx >> 8;
    int i = pc & 31;                // pair index within head (0..31)
    int s = token & (SS - 1);       // seq position
    float inv = __expf(-logf(10000.0f) * ((float)i / 32.0f));
    float ang = (float)s * inv;
    float c, sn;
    __sincosf(ang, &sn, &c);
    // higher-accuracy path for the trig (matches fp32 ref closely enough):
    c = cosf(ang); sn = sinf(ang);
    float* p = x + (size_t)token * DAA + 2 * pc;
    float x1 = p[0], x2 = p[1];
    p[0] = x1 * c - x2 * sn;
    p[1] = x1 * sn + x2 * c;
}

// ---------------- Flash attention (fp32, online softmax) ----------------
// grid: (S/64, B*H); 256 threads = 8 warps; warp w owns query rows [w*8, w*8+8)
// lane owns score column 'lane' (of 32) and output dims {lane, lane+32}.
// icl_mode=1: attend kg < qg, plus (0,0). icl_mode=0: attend kg <= qg.
__global__ void __launch_bounds__(256) flash_kernel(
    const float* __restrict__ Qm, const float* __restrict__ Km,
    const float* __restrict__ Vm, float* __restrict__ Om, int icl_mode)
{
    __shared__ float Qs[64][64];    // row-major, float4 broadcast reads
    __shared__ float Kt[64][33];    // transposed: Kt[d][key], conflict-free
    __shared__ float Vs[32][68];    // padded for aligned float4 stores
    __shared__ float Ps[64][32];    // probabilities

    const int qt = blockIdx.x;
    const int bh = blockIdx.y;
    const int b = bh / HH, h = bh % HH;
    const int tid = threadIdx.x;
    const int warp = tid >> 5, lane = tid & 31;
    const int qg0 = qt * 64;
    const int r0 = warp * 8;

    const float* Qb = Qm + (size_t)b * SS * DAA + h * DHH;
    const float* Kb = Km + (size_t)b * SS * DAA + h * DHH;
    const float* Vb = Vm + (size_t)b * SS * DAA + h * DHH;

    // load Q tile: 64 rows x 16 float4
    for (int i = tid; i < 64 * 16; i += 256) {
        int r = i >> 4, c4 = i & 15;
        *(float4*)&Qs[r][c4 * 4] = *(const float4*)&Qb[(size_t)(qg0 + r) * DAA + c4 * 4];
    }

    float m[8], lsum[8], o0[8], o1[8];
#pragma unroll
    for (int r = 0; r < 8; r++) { m[r] = -1e30f; lsum[r] = 0.f; o0[r] = 0.f; o1[r] = 0.f; }

    const int ktmax = (qg0 + 63) >> 5;   // inclusive
    for (int kt = 0; kt <= ktmax; kt++) {
        const int kg0 = kt * 32;
        __syncthreads();   // prior-tile reads done (also covers Qs load on iter 0)
        // load K (transposed) + V: 32 keys x 64 dims each
        for (int i = tid; i < 32 * 16; i += 256) {
            int c = i >> 4, d4 = i & 15;
            float4 k4 = *(const float4*)&Kb[(size_t)(kg0 + c) * DAA + d4 * 4];
            Kt[d4 * 4 + 0][c] = k4.x;
            Kt[d4 * 4 + 1][c] = k4.y;
            Kt[d4 * 4 + 2][c] = k4.z;
            Kt[d4 * 4 + 3][c] = k4.w;
            *(float4*)&Vs[c][d4 * 4] = *(const float4*)&Vb[(size_t)(kg0 + c) * DAA + d4 * 4];
        }
        __syncthreads();

        // scores: lane -> key column (kg0+lane)
        float sc[8];
#pragma unroll
        for (int r = 0; r < 8; r++) sc[r] = 0.f;
#pragma unroll
        for (int d4 = 0; d4 < 16; d4++) {
            float k0 = Kt[d4 * 4 + 0][lane];
            float k1 = Kt[d4 * 4 + 1][lane];
            float k2 = Kt[d4 * 4 + 2][lane];
            float k3 = Kt[d4 * 4 + 3][lane];
#pragma unroll
            for (int r = 0; r < 8; r++) {
                float4 q4 = *(float4*)&Qs[r0 + r][d4 * 4];
                sc[r] += q4.x * k0 + q4.y * k1 + q4.z * k2 + q4.w * k3;
            }
        }
        const int kg = kg0 + lane;
#pragma unroll
        for (int r = 0; r < 8; r++) {
            int qg = qg0 + r0 + r;
            bool allow = icl_mode ? (kg < qg || (qg == 0 && kg == 0)) : (kg <= qg);
            float s = allow ? sc[r] * SCALE_ATTN : -1e30f;
            float mx = s;
#pragma unroll
            for (int o = 16; o > 0; o >>= 1) mx = fmaxf(mx, __shfl_xor_sync(0xffffffffu, mx, o));
            float mnew = fmaxf(m[r], mx);
            float p = expf(s - mnew);
            float rs = p;
#pragma unroll
            for (int o = 16; o > 0; o >>= 1) rs += __shfl_xor_sync(0xffffffffu, rs, o);
            float corr = expf(m[r] - mnew);
            lsum[r] = lsum[r] * corr + rs;
            o0[r] *= corr; o1[r] *= corr;
            m[r] = mnew;
            Ps[r0 + r][lane] = p;
        }
        __syncwarp();
        // PV: lane accumulates output dims {lane, lane+32}
#pragma unroll
        for (int t = 0; t < 32; t++) {
            float va = Vs[t][lane];
            float vb = Vs[t][lane + 32];
#pragma unroll
            for (int r = 0; r < 8; r++) {
                float p = Ps[r0 + r][t];
                o0[r] += p * va;
                o1[r] += p * vb;
            }
        }
    }

    float* Ob = Om + (size_t)b * SS * DAA + h * DHH;
#pragma unroll
    for (int r = 0; r < 8; r++) {
        float inv = 1.0f / lsum[r];
        size_t off = (size_t)(qg0 + r0 + r) * DAA;
        Ob[off + lane]      = o0[r] * inv;
        Ob[off + lane + 32] = o1[r] * inv;
    }
}

// ---------------- host driver ----------------
extern "C" void kernel_launch(void* const* d_in, const int* in_sizes, int n_in,
                              void* d_out, int out_size)
{
    const float* cov_in  = (const float*)d_in[0];
    const float* tgt_in  = (const float*)d_in[1];
    const float* fu_in   = (const float*)d_in[2];
    const float* fc1w    = (const float*)d_in[3];
    const float* fc1b    = (const float*)d_in[4];
    const float* fc2w    = (const float*)d_in[5];
    const float* fc2b    = (const float*)d_in[6];
    const float* icl_wq  = (const float*)d_in[7];
    const float* icl_wk  = (const float*)d_in[8];
    const float* icl_wv  = (const float*)d_in[9];
    const float* icl_wo  = (const float*)d_in[10];
    const float* cov_wq  = (const float*)d_in[11];
    const float* cov_wk  = (const float*)d_in[12];
    const float* cov_wv  = (const float*)d_in[13];
    const float* cov_wo  = (const float*)d_in[14];
    const float* ln_cm_g = (const float*)d_in[15];
    const float* ln_cm_b = (const float*)d_in[16];
    const float* ln_ia_g = (const float*)d_in[17];
    const float* ln_ia_b = (const float*)d_in[18];
    const float* ln_im_g = (const float*)d_in[19];
    const float* ln_im_b = (const float*)d_in[20];

    float* out_cov = (float*)d_out;
    float* out_tgt = out_cov + (size_t)NTOK * EE;
    float* out_fu  = out_tgt + (size_t)NTOK * EE;

    float *ln, *mid, *q, *qp, *kp, *vp, *ao;
    cudaGetSymbolAddress((void**)&ln,  g_ln);
    cudaGetSymbolAddress((void**)&mid, g_mid);
    cudaGetSymbolAddress((void**)&q,   g_q);
    cudaGetSymbolAddress((void**)&qp,  g_qp);
    cudaGetSymbolAddress((void**)&kp,  g_kp);
    cudaGetSymbolAddress((void**)&vp,  g_vp);
    cudaGetSymbolAddress((void**)&ao,  g_ao);

    const dim3 thr(256);
    const dim3 gM (NTOK / 128, 1);    // unused helper
    const dim3 gFC1(DMLP / 128, NTOK / 128);
    const dim3 gFC2(EE   / 128, NTOK / 128);
    const dim3 gPRJ(DAA  / 128, NTOK / 128);
    const dim3 gWO (EE   / 128, NTOK / 128);
    const dim3 gFLASH(SS / 64, BB * HH);

    // cov = covariates + MLP(LN(covariates))
    ln_kernel<<<NTOK, thr>>>(cov_in, ln_cm_g, ln_cm_b, ln);
    gemm_kernel<1><<<gFC1, thr>>>(ln, fc1w, fc1b, nullptr, mid, NTOK, DMLP, EE);
    gemm_kernel<2><<<gFC2, thr>>>(mid, fc2w, fc2b, cov_in, out_cov, NTOK, EE, DMLP);

    // tgt = targets + MLP(LN(functional_update))
    ln_kernel<<<NTOK, thr>>>(fu_in, ln_im_g, ln_im_b, ln);
    gemm_kernel<1><<<gFC1, thr>>>(ln, fc1w, fc1b, nullptr, mid, NTOK, DMLP, EE);
    gemm_kernel<2><<<gFC2, thr>>>(mid, fc2w, fc2b, tgt_in, out_tgt, NTOK, EE, DMLP);

    // q = LN(cov)
    ln_kernel<<<NTOK, thr>>>(out_cov, ln_ia_g, ln_ia_b, q);

    // ---- ICL attention: fu = functional_update + attn(q, q, tgt) ----
    gemm_kernel<0><<<gPRJ, thr>>>(q,       icl_wq, nullptr, nullptr, qp, NTOK, DAA, EE);
    gemm_kernel<0><<<gPRJ, thr>>>(q,       icl_wk, nullptr, nullptr, kp, NTOK, DAA, EE);
    gemm_kernel<0><<<gPRJ, thr>>>(out_tgt, icl_wv, nullptr, nullptr, vp, NTOK, DAA, EE);
    rope_kernel<<<NTOK, thr>>>(qp);
    rope_kernel<<<NTOK, thr>>>(kp);
    flash_kernel<<<gFLASH, thr>>>(qp, kp, vp, ao, 1);
    gemm_kernel<3><<<gWO, thr>>>(ao, icl_wo, nullptr, fu_in, out_fu, NTOK, EE, DAA);

    // ---- COV attention: cov = cov + attn(q, q, q) ----
    gemm_kernel<0><<<gPRJ, thr>>>(q, cov_wq, nullptr, nullptr, qp, NTOK, DAA, EE);
    gemm_kernel<0><<<gPRJ, thr>>>(q, cov_wk, nullptr, nullptr, kp, NTOK, DAA, EE);
    gemm_kernel<0><<<gPRJ, thr>>>(q, cov_wv, nullptr, nullptr, vp, NTOK, DAA, EE);
    rope_kernel<<<NTOK, thr>>>(qp);
    rope_kernel<<<NTOK, thr>>>(kp);
    flash_kernel<<<gFLASH, thr>>>(qp, kp, vp, ao, 0);
    gemm_kernel<3><<<gWO, thr>>>(ao, cov_wo, nullptr, out_cov, out_cov, NTOK, EE, DAA);
}

// round 3
// speedup vs baseline: 1.5107x; 1.5107x over previous
#include <cuda_runtime.h>
#include <cuda_bf16.h>
#include <math.h>
#include <stdint.h>

#define BB 2
#define SS 2048
#define EE 1024
#define HH 8
#define DHH 64
#define DAA 512
#define DMLP 2048
#define NTOK 4096
#define SCALE_ATTN 0.04419417382415922f
#define LN_EPS 1e-5f
#define SA 40   // bf16 row stride in smem (20 words -> conflict-free fragment LDS)

// ---------------- scratch ----------------
__device__ float g_ln [NTOK * EE];
__device__ float g_mid[NTOK * DMLP];
__device__ float g_q  [NTOK * EE];
__device__ float g_qp [NTOK * DAA];
__device__ float g_kp [NTOK * DAA];
__device__ float g_vp [NTOK * DAA];
__device__ float g_ao [NTOK * DAA];

// ---------------- helpers ----------------
__device__ __forceinline__ uint32_t pk2(__nv_bfloat16 a, __nv_bfloat16 b) {
    uint16_t ra = *reinterpret_cast<uint16_t*>(&a);
    uint16_t rb = *reinterpret_cast<uint16_t*>(&b);
    return (uint32_t)ra | ((uint32_t)rb << 16);
}
__device__ __forceinline__ void split1(float x, __nv_bfloat16& h, __nv_bfloat16& l) {
    h = __float2bfloat16(x);
    l = __float2bfloat16(x - __bfloat162float(h));
}
__device__ __forceinline__ void mma16816(float* c, const uint32_t* a, const uint32_t* b) {
    asm volatile(
        "mma.sync.aligned.m16n8k16.row.col.f32.bf16.bf16.f32 "
        "{%0,%1,%2,%3}, {%4,%5,%6,%7}, {%8,%9}, {%0,%1,%2,%3};"
        : "+f"(c[0]), "+f"(c[1]), "+f"(c[2]), "+f"(c[3])
        : "r"(a[0]), "r"(a[1]), "r"(a[2]), "r"(a[3]), "r"(b[0]), "r"(b[1]));
}

__device__ __forceinline__ float block_reduce_sum(float v) {
    __shared__ float red[32];
    int lane = threadIdx.x & 31, w = threadIdx.x >> 5;
#pragma unroll
    for (int o = 16; o > 0; o >>= 1) v += __shfl_xor_sync(0xffffffffu, v, o);
    __syncthreads();
    if (lane == 0) red[w] = v;
    __syncthreads();
    v = (lane < 8) ? red[lane] : 0.f;
#pragma unroll
    for (int o = 16; o > 0; o >>= 1) v += __shfl_xor_sync(0xffffffffu, v, o);
    return v;
}

// ---------------- LayerNorm ----------------
__global__ void ln_kernel(const float* __restrict__ x, const float* __restrict__ g,
                          const float* __restrict__ b, float* __restrict__ out) {
    int row = blockIdx.x;
    const float* xr = x + (size_t)row * EE;
    float* orow = out + (size_t)row * EE;
    int tid = threadIdx.x;
    float v[4]; float s = 0.f;
#pragma unroll
    for (int i = 0; i < 4; i++) { v[i] = xr[tid + 256 * i]; s += v[i]; }
    float mean = block_reduce_sum(s) * (1.0f / EE);
    float sq = 0.f;
#pragma unroll
    for (int i = 0; i < 4; i++) { float d = v[i] - mean; sq += d * d; }
    float var = block_reduce_sum(sq) * (1.0f / EE);
    float rstd = rsqrtf(var + LN_EPS);
#pragma unroll
    for (int i = 0; i < 4; i++) {
        int c = tid + 256 * i;
        orow[c] = (v[i] - mean) * rstd * g[c] + b[c];
    }
}

// ---------------- HMMA bf16-split GEMM: 128x128 tile, 8 warps of 64x32 ----------------
// MODE 0: C = AB   1: gelu(AB+bias)   2: AB+bias+R   3: AB+R
template<int MODE>
__global__ void __launch_bounds__(256, 2) gemm_hmma(
    const float* __restrict__ A, const float* __restrict__ Bw,
    const float* __restrict__ bias, const float* __restrict__ R,
    float* __restrict__ C, int M, int N, int K)
{
    __shared__ __align__(16) uint16_t Ah[128 * SA], Al[128 * SA];
    __shared__ __align__(16) uint16_t Bh[128 * SA], Bl[128 * SA];

    const int tid = threadIdx.x;
    const int warp = tid >> 5, lane = tid & 31;
    const int wm = warp & 1, wn = warp >> 1;           // 2 x 4 warp grid
    const int m0 = blockIdx.y * 128, n0 = blockIdx.x * 128;
    const int q = lane & 3, r = lane >> 2;

    float acc[4][4][4];
#pragma unroll
    for (int i = 0; i < 4; i++)
#pragma unroll
        for (int j = 0; j < 4; j++)
#pragma unroll
            for (int k = 0; k < 4; k++) acc[i][j][k] = 0.f;

    for (int k0 = 0; k0 < K; k0 += 32) {
        // A chunk: 128 x 32 fp32, convert+split into Ah/Al (row-major, stride SA)
#pragma unroll
        for (int i = 0; i < 4; i++) {
            int idx = tid + i * 256;
            int m = idx >> 3, kq = (idx & 7) * 4;
            float4 v = *(const float4*)&A[(size_t)(m0 + m) * K + k0 + kq];
            __nv_bfloat16 h0, h1, h2, h3, l0, l1, l2, l3;
            split1(v.x, h0, l0); split1(v.y, h1, l1);
            split1(v.z, h2, l2); split1(v.w, h3, l3);
            *(uint2*)&Ah[m * SA + kq] = make_uint2(pk2(h0, h1), pk2(h2, h3));
            *(uint2*)&Al[m * SA + kq] = make_uint2(pk2(l0, l1), pk2(l2, l3));
        }
        // B chunk: 32 x 128 fp32 -> transposed Bs[n][k] bf16 (k contiguous pairs)
#pragma unroll
        for (int i = 0; i < 8; i++) {
            int idx = tid + i * 256;             // 0..2047
            int n = idx & 127, kp = idx >> 7;    // kp 0..15
            float b0f = Bw[(size_t)(k0 + 2 * kp) * N + n0 + n];
            float b1f = Bw[(size_t)(k0 + 2 * kp + 1) * N + n0 + n];
            __nv_bfloat16 h0, h1, l0, l1;
            split1(b0f, h0, l0); split1(b1f, h1, l1);
            *(uint32_t*)&Bh[n * SA + 2 * kp] = pk2(h0, h1);
            *(uint32_t*)&Bl[n * SA + 2 * kp] = pk2(l0, l1);
        }
        __syncthreads();

#pragma unroll
        for (int ks = 0; ks < 2; ks++) {
            const int kk = ks * 16;
            uint32_t bhf[4][2], blf[4][2];
#pragma unroll
            for (int nt = 0; nt < 4; nt++) {
                int n = wn * 32 + nt * 8 + r;
                bhf[nt][0] = *(const uint32_t*)&Bh[n * SA + kk + q * 2];
                bhf[nt][1] = *(const uint32_t*)&Bh[n * SA + kk + q * 2 + 8];
                blf[nt][0] = *(const uint32_t*)&Bl[n * SA + kk + q * 2];
                blf[nt][1] = *(const uint32_t*)&Bl[n * SA + kk + q * 2 + 8];
            }
#pragma unroll
            for (int mt = 0; mt < 4; mt++) {
                int m = wm * 64 + mt * 16 + r;
                uint32_t ahf[4], alf[4];
                ahf[0] = *(const uint32_t*)&Ah[m * SA + kk + q * 2];
                ahf[1] = *(const uint32_t*)&Ah[(m + 8) * SA + kk + q * 2];
                ahf[2] = *(const uint32_t*)&Ah[m * SA + kk + q * 2 + 8];
                ahf[3] = *(const uint32_t*)&Ah[(m + 8) * SA + kk + q * 2 + 8];
                alf[0] = *(const uint32_t*)&Al[m * SA + kk + q * 2];
                alf[1] = *(const uint32_t*)&Al[(m + 8) * SA + kk + q * 2];
                alf[2] = *(const uint32_t*)&Al[m * SA + kk + q * 2 + 8];
                alf[3] = *(const uint32_t*)&Al[(m + 8) * SA + kk + q * 2 + 8];
#pragma unroll
                for (int nt = 0; nt < 4; nt++) {
                    mma16816(acc[mt][nt], ahf, bhf[nt]);
                    mma16816(acc[mt][nt], ahf, blf[nt]);
                    mma16816(acc[mt][nt], alf, bhf[nt]);
                }
            }
        }
        __syncthreads();
    }

    // epilogue: c0/c1 -> (row, col..col+1), c2/c3 -> (row+8, ...)
#pragma unroll
    for (int mt = 0; mt < 4; mt++) {
#pragma unroll
        for (int nt = 0; nt < 4; nt++) {
            int row = m0 + wm * 64 + mt * 16 + r;
            int col = n0 + wn * 32 + nt * 8 + q * 2;
#pragma unroll
            for (int half = 0; half < 2; half++) {
                int rr2 = row + half * 8;
                float v0 = acc[mt][nt][half * 2 + 0];
                float v1 = acc[mt][nt][half * 2 + 1];
                size_t gidx = (size_t)rr2 * N + col;
                if (MODE == 1) {
                    v0 += bias[col];
                    v1 += bias[col + 1];
                    v0 = 0.5f * v0 * (1.0f + erff(v0 * 0.70710678118654752f));
                    v1 = 0.5f * v1 * (1.0f + erff(v1 * 0.70710678118654752f));
                } else if (MODE == 2) {
                    float2 rv = *(const float2*)&R[gidx];
                    v0 += bias[col] + rv.x;
                    v1 += bias[col + 1] + rv.y;
                } else if (MODE == 3) {
                    float2 rv = *(const float2*)&R[gidx];
                    v0 += rv.x;
                    v1 += rv.y;
                }
                *(float2*)&C[gidx] = make_float2(v0, v1);
            }
        }
    }
}

// ---------------- RoPE ----------------
__global__ void rope_kernel(float* __restrict__ x) {
    int idx = blockIdx.x * blockDim.x + threadIdx.x;
    int pc = idx & 255;
    int token = idx >> 8;
    int i = pc & 31;
    int s = token & (SS - 1);
    float inv = __expf(-logf(10000.0f) * ((float)i / 32.0f));
    float ang = (float)s * inv;
    float c = cosf(ang), sn = sinf(ang);
    float* p = x + (size_t)token * DAA + 2 * pc;
    float x1 = p[0], x2 = p[1];
    p[0] = x1 * c - x2 * sn;
    p[1] = x1 * sn + x2 * c;
}

// ---------------- Flash attention (fp32, online softmax) ----------------
__global__ void __launch_bounds__(256) flash_kernel(
    const float* __restrict__ Qm, const float* __restrict__ Km,
    const float* __restrict__ Vm, float* __restrict__ Om, int icl_mode)
{
    __shared__ float Qs[64][64];
    __shared__ float Kt[64][33];
    __shared__ float Vs[32][68];
    __shared__ float Ps[64][32];

    const int qt = blockIdx.x;
    const int bh = blockIdx.y;
    const int b = bh / HH, h = bh % HH;
    const int tid = threadIdx.x;
    const int warp = tid >> 5, lane = tid & 31;
    const int qg0 = qt * 64;
    const int r0 = warp * 8;

    const float* Qb = Qm + (size_t)b * SS * DAA + h * DHH;
    const float* Kb = Km + (size_t)b * SS * DAA + h * DHH;
    const float* Vb = Vm + (size_t)b * SS * DAA + h * DHH;

    for (int i = tid; i < 64 * 16; i += 256) {
        int r = i >> 4, c4 = i & 15;
        *(float4*)&Qs[r][c4 * 4] = *(const float4*)&Qb[(size_t)(qg0 + r) * DAA + c4 * 4];
    }

    float m[8], lsum[8], o0[8], o1[8];
#pragma unroll
    for (int r = 0; r < 8; r++) { m[r] = -1e30f; lsum[r] = 0.f; o0[r] = 0.f; o1[r] = 0.f; }

    const int ktmax = (qg0 + 63) >> 5;
    for (int kt = 0; kt <= ktmax; kt++) {
        const int kg0 = kt * 32;
        __syncthreads();
        for (int i = tid; i < 32 * 16; i += 256) {
            int c = i >> 4, d4 = i & 15;
            float4 k4 = *(const float4*)&Kb[(size_t)(kg0 + c) * DAA + d4 * 4];
            Kt[d4 * 4 + 0][c] = k4.x;
            Kt[d4 * 4 + 1][c] = k4.y;
            Kt[d4 * 4 + 2][c] = k4.z;
            Kt[d4 * 4 + 3][c] = k4.w;
            *(float4*)&Vs[c][d4 * 4] = *(const float4*)&Vb[(size_t)(kg0 + c) * DAA + d4 * 4];
        }
        __syncthreads();

        float sc[8];
#pragma unroll
        for (int r = 0; r < 8; r++) sc[r] = 0.f;
#pragma unroll
        for (int d4 = 0; d4 < 16; d4++) {
            float k0 = Kt[d4 * 4 + 0][lane];
            float k1 = Kt[d4 * 4 + 1][lane];
            float k2 = Kt[d4 * 4 + 2][lane];
            float k3 = Kt[d4 * 4 + 3][lane];
#pragma unroll
            for (int r = 0; r < 8; r++) {
                float4 q4 = *(float4*)&Qs[r0 + r][d4 * 4];
                sc[r] += q4.x * k0 + q4.y * k1 + q4.z * k2 + q4.w * k3;
            }
        }
        const int kg = kg0 + lane;
#pragma unroll
        for (int r = 0; r < 8; r++) {
            int qg = qg0 + r0 + r;
            bool allow = icl_mode ? (kg < qg || (qg == 0 && kg == 0)) : (kg <= qg);
            float s = allow ? sc[r] * SCALE_ATTN : -1e30f;
            float mx = s;
#pragma unroll
            for (int o = 16; o > 0; o >>= 1) mx = fmaxf(mx, __shfl_xor_sync(0xffffffffu, mx, o));
            float mnew = fmaxf(m[r], mx);
            float p = expf(s - mnew);
            float rs = p;
#pragma unroll
            for (int o = 16; o > 0; o >>= 1) rs += __shfl_xor_sync(0xffffffffu, rs, o);
            float corr = expf(m[r] - mnew);
            lsum[r] = lsum[r] * corr + rs;
            o0[r] *= corr; o1[r] *= corr;
            m[r] = mnew;
            Ps[r0 + r][lane] = p;
        }
        __syncwarp();
#pragma unroll
        for (int t = 0; t < 32; t++) {
            float va = Vs[t][lane];
            float vb = Vs[t][lane + 32];
#pragma unroll
            for (int r = 0; r < 8; r++) {
                float p = Ps[r0 + r][t];
                o0[r] += p * va;
                o1[r] += p * vb;
            }
        }
    }

    float* Ob = Om + (size_t)b * SS * DAA + h * DHH;
#pragma unroll
    for (int r = 0; r < 8; r++) {
        float inv = 1.0f / lsum[r];
        size_t off = (size_t)(qg0 + r0 + r) * DAA;
        Ob[off + lane]      = o0[r] * inv;
        Ob[off + lane + 32] = o1[r] * inv;
    }
}

// ---------------- host driver ----------------
extern "C" void kernel_launch(void* const* d_in, const int* in_sizes, int n_in,
                              void* d_out, int out_size)
{
    const float* cov_in  = (const float*)d_in[0];
    const float* tgt_in  = (const float*)d_in[1];
    const float* fu_in   = (const float*)d_in[2];
    const float* fc1w    = (const float*)d_in[3];
    const float* fc1b    = (const float*)d_in[4];
    const float* fc2w    = (const float*)d_in[5];
    const float* fc2b    = (const float*)d_in[6];
    const float* icl_wq  = (const float*)d_in[7];
    const float* icl_wk  = (const float*)d_in[8];
    const float* icl_wv  = (const float*)d_in[9];
    const float* icl_wo  = (const float*)d_in[10];
    const float* cov_wq  = (const float*)d_in[11];
    const float* cov_wk  = (const float*)d_in[12];
    const float* cov_wv  = (const float*)d_in[13];
    const float* cov_wo  = (const float*)d_in[14];
    const float* ln_cm_g = (const float*)d_in[15];
    const float* ln_cm_b = (const float*)d_in[16];
    const float* ln_ia_g = (const float*)d_in[17];
    const float* ln_ia_b = (const float*)d_in[18];
    const float* ln_im_g = (const float*)d_in[19];
    const float* ln_im_b = (const float*)d_in[20];

    float* out_cov = (float*)d_out;
    float* out_tgt = out_cov + (size_t)NTOK * EE;
    float* out_fu  = out_tgt + (size_t)NTOK * EE;

    float *ln, *mid, *q, *qp, *kp, *vp, *ao;
    cudaGetSymbolAddress((void**)&ln,  g_ln);
    cudaGetSymbolAddress((void**)&mid, g_mid);
    cudaGetSymbolAddress((void**)&q,   g_q);
    cudaGetSymbolAddress((void**)&qp,  g_qp);
    cudaGetSymbolAddress((void**)&kp,  g_kp);
    cudaGetSymbolAddress((void**)&vp,  g_vp);
    cudaGetSymbolAddress((void**)&ao,  g_ao);

    const dim3 thr(256);
    const dim3 gFC1(DMLP / 128, NTOK / 128);
    const dim3 gFC2(EE   / 128, NTOK / 128);
    const dim3 gPRJ(DAA  / 128, NTOK / 128);
    const dim3 gWO (EE   / 128, NTOK / 128);
    const dim3 gFLASH(SS / 64, BB * HH);

    // cov = covariates + MLP(LN(covariates))
    ln_kernel<<<NTOK, thr>>>(cov_in, ln_cm_g, ln_cm_b, ln);
    gemm_hmma<1><<<gFC1, thr>>>(ln, fc1w, fc1b, nullptr, mid, NTOK, DMLP, EE);
    gemm_hmma<2><<<gFC2, thr>>>(mid, fc2w, fc2b, cov_in, out_cov, NTOK, EE, DMLP);

    // tgt = targets + MLP(LN(functional_update))
    ln_kernel<<<NTOK, thr>>>(fu_in, ln_im_g, ln_im_b, ln);
    gemm_hmma<1><<<gFC1, thr>>>(ln, fc1w, fc1b, nullptr, mid, NTOK, DMLP, EE);
    gemm_hmma<2><<<gFC2, thr>>>(mid, fc2w, fc2b, tgt_in, out_tgt, NTOK, EE, DMLP);

    // q = LN(cov)
    ln_kernel<<<NTOK, thr>>>(out_cov, ln_ia_g, ln_ia_b, q);

    // ICL attention: fu = functional_update + attn(q, q, tgt)
    gemm_hmma<0><<<gPRJ, thr>>>(q,       icl_wq, nullptr, nullptr, qp, NTOK, DAA, EE);
    gemm_hmma<0><<<gPRJ, thr>>>(q,       icl_wk, nullptr, nullptr, kp, NTOK, DAA, EE);
    gemm_hmma<0><<<gPRJ, thr>>>(out_tgt, icl_wv, nullptr, nullptr, vp, NTOK, DAA, EE);
    rope_kernel<<<NTOK, thr>>>(qp);
    rope_kernel<<<NTOK, thr>>>(kp);
    flash_kernel<<<gFLASH, thr>>>(qp, kp, vp, ao, 1);
    gemm_hmma<3><<<gWO, thr>>>(ao, icl_wo, nullptr, fu_in, out_fu, NTOK, EE, DAA);

    // COV attention: cov = cov + attn(q, q, q)
    gemm_hmma<0><<<gPRJ, thr>>>(q, cov_wq, nullptr, nullptr, qp, NTOK, DAA, EE);
    gemm_hmma<0><<<gPRJ, thr>>>(q, cov_wk, nullptr, nullptr, kp, NTOK, DAA, EE);
    gemm_hmma<0><<<gPRJ, thr>>>(q, cov_wv, nullptr, nullptr, vp, NTOK, DAA, EE);
    rope_kernel<<<NTOK, thr>>>(qp);
    rope_kernel<<<NTOK, thr>>>(kp);
    flash_kernel<<<gFLASH, thr>>>(qp, kp, vp, ao, 0);
    gemm_hmma<3><<<gWO, thr>>>(ao, cov_wo, nullptr, out_cov, out_cov, NTOK, EE, DAA);
}

// round 4
// speedup vs baseline: 1.8024x; 1.1931x over previous
#include <cuda_runtime.h>
#include <cuda_bf16.h>
#include <math.h>
#include <stdint.h>

#define BB 2
#define SS 2048
#define EE 1024
#define HH 8
#define DHH 64
#define DAA 512
#define DMLP 2048
#define NTOK 4096
#define SCALE_ATTN 0.04419417382415922f
#define LN_EPS 1e-5f

// GEMM smem: per stage, 4 planes of 128 rows x 32 bf16, row stride 40 bf16 (80B)
#define ROWB 80
#define PLANE_B 10240          // 128 * 80
#define STAGE_B 40960          // 4 planes
#define SMEM_GEMM (2 * STAGE_B)

// ---------------- fp32 scratch ----------------
__device__ float g_qp[NTOK * DAA];
__device__ float g_kp[NTOK * DAA];
__device__ float g_vp[NTOK * DAA];

// ---------------- bf16 hi/lo planes ----------------
__device__ uint16_t pLNh[NTOK * EE],   pLNl[NTOK * EE];
__device__ uint16_t pMIDh[NTOK * DMLP], pMIDl[NTOK * DMLP];
__device__ uint16_t pQh[NTOK * EE],    pQl[NTOK * EE];
__device__ uint16_t pTGTh[NTOK * EE],  pTGTl[NTOK * EE];
__device__ uint16_t pAOh[NTOK * DAA],  pAOl[NTOK * DAA];

__device__ uint16_t pW1h[DMLP * EE],  pW1l[DMLP * EE];    // [N][K] = [2048][1024]
__device__ uint16_t pW2h[EE * DMLP],  pW2l[EE * DMLP];    // [1024][2048]
__device__ uint16_t pIQh[DAA * EE],   pIQl[DAA * EE];
__device__ uint16_t pIKh[DAA * EE],   pIKl[DAA * EE];
__device__ uint16_t pIVh[DAA * EE],   pIVl[DAA * EE];
__device__ uint16_t pIOh[EE * DAA],   pIOl[EE * DAA];
__device__ uint16_t pCQh[DAA * EE],   pCQl[DAA * EE];
__device__ uint16_t pCKh[DAA * EE],   pCKl[DAA * EE];
__device__ uint16_t pCVh[DAA * EE],   pCVl[DAA * EE];
__device__ uint16_t pCOh[EE * DAA],   pCOl[EE * DAA];

// ---------------- helpers ----------------
__device__ __forceinline__ uint32_t pk2(__nv_bfloat16 a, __nv_bfloat16 b) {
    uint16_t ra = *reinterpret_cast<uint16_t*>(&a);
    uint16_t rb = *reinterpret_cast<uint16_t*>(&b);
    return (uint32_t)ra | ((uint32_t)rb << 16);
}
__device__ __forceinline__ void split1(float x, __nv_bfloat16& h, __nv_bfloat16& l) {
    h = __float2bfloat16(x);
    l = __float2bfloat16(x - __bfloat162float(h));
}
__device__ __forceinline__ void mma16816(float* c, const uint32_t* a, const uint32_t* b) {
    asm volatile(
        "mma.sync.aligned.m16n8k16.row.col.f32.bf16.bf16.f32 "
        "{%0,%1,%2,%3}, {%4,%5,%6,%7}, {%8,%9}, {%0,%1,%2,%3};"
        : "+f"(c[0]), "+f"(c[1]), "+f"(c[2]), "+f"(c[3])
        : "r"(a[0]), "r"(a[1]), "r"(a[2]), "r"(a[3]), "r"(b[0]), "r"(b[1]));
}
__device__ __forceinline__ void ldsm4(uint32_t& r0, uint32_t& r1, uint32_t& r2, uint32_t& r3,
                                      uint32_t addr) {
    asm volatile("ldmatrix.sync.aligned.m8n8.x4.shared.b16 {%0,%1,%2,%3}, [%4];"
                 : "=r"(r0), "=r"(r1), "=r"(r2), "=r"(r3) : "r"(addr));
}
__device__ __forceinline__ void cpa16(uint32_t s, const void* g) {
    asm volatile("cp.async.ca.shared.global [%0], [%1], 16;" :: "r"(s), "l"(g));
}
__device__ __forceinline__ void cpa_commit() {
    asm volatile("cp.async.commit_group;" ::: "memory");
}
template<int N>
__device__ __forceinline__ void cpa_wait() {
    asm volatile("cp.async.wait_group %0;" :: "n"(N) : "memory");
}

__device__ __forceinline__ float block_reduce_sum(float v) {
    __shared__ float red[32];
    int lane = threadIdx.x & 31, w = threadIdx.x >> 5;
#pragma unroll
    for (int o = 16; o > 0; o >>= 1) v += __shfl_xor_sync(0xffffffffu, v, o);
    __syncthreads();
    if (lane == 0) red[w] = v;
    __syncthreads();
    v = (lane < 8) ? red[lane] : 0.f;
#pragma unroll
    for (int o = 16; o > 0; o >>= 1) v += __shfl_xor_sync(0xffffffffu, v, o);
    return v;
}

// ---------------- LayerNorm -> bf16 hi/lo planes ----------------
__global__ void ln_split(const float* __restrict__ x, const float* __restrict__ g,
                         const float* __restrict__ b,
                         uint16_t* __restrict__ oh, uint16_t* __restrict__ ol) {
    int row = blockIdx.x, t = threadIdx.x;
    float4 v = *(const float4*)&x[(size_t)row * EE + 4 * t];
    float s = v.x + v.y + v.z + v.w;
    float mean = block_reduce_sum(s) * (1.0f / EE);
    float d0 = v.x - mean, d1 = v.y - mean, d2 = v.z - mean, d3 = v.w - mean;
    float var = block_reduce_sum(d0 * d0 + d1 * d1 + d2 * d2 + d3 * d3) * (1.0f / EE);
    float rstd = rsqrtf(var + LN_EPS);
    float4 gg = *(const float4*)&g[4 * t];
    float4 bb = *(const float4*)&b[4 * t];
    float y0 = d0 * rstd * gg.x + bb.x;
    float y1 = d1 * rstd * gg.y + bb.y;
    float y2 = d2 * rstd * gg.z + bb.z;
    float y3 = d3 * rstd * gg.w + bb.w;
    __nv_bfloat16 h0, h1, h2, h3, l0, l1, l2, l3;
    split1(y0, h0, l0); split1(y1, h1, l1); split1(y2, h2, l2); split1(y3, h3, l3);
    size_t off = (size_t)row * EE + 4 * t;
    *(uint2*)&oh[off] = make_uint2(pk2(h0, h1), pk2(h2, h3));
    *(uint2*)&ol[off] = make_uint2(pk2(l0, l1), pk2(l2, l3));
}

// ---------------- weight fp32 [K,N] -> planes [N][K] ----------------
__global__ void convB(const float* __restrict__ W,
                      uint16_t* __restrict__ Bh, uint16_t* __restrict__ Bl, int K, int N) {
    __shared__ float ts[64][129];
    int nt = blockIdx.x, kt = blockIdx.y, tid = threadIdx.x;
    int k0 = kt * 64, n0 = nt * 128;
#pragma unroll
    for (int i = 0; i < 32; i++) {
        int idx = tid + i * 256;
        int kk = idx >> 7, nn = idx & 127;
        ts[kk][nn] = W[(size_t)(k0 + kk) * N + n0 + nn];
    }
    __syncthreads();
#pragma unroll
    for (int j = 0; j < 4; j++) {
        int job = tid + j * 256;
        int n = job >> 3, kg = (job & 7) * 8;
        __nv_bfloat16 h[8], l[8];
#pragma unroll
        for (int i = 0; i < 8; i++) split1(ts[kg + i][n], h[i], l[i]);
        uint4 uh = make_uint4(pk2(h[0], h[1]), pk2(h[2], h[3]), pk2(h[4], h[5]), pk2(h[6], h[7]));
        uint4 ul = make_uint4(pk2(l[0], l[1]), pk2(l[2], l[3]), pk2(l[4], l[5]), pk2(l[6], l[7]));
        size_t off = (size_t)(n0 + n) * K + k0 + kg;
        *(uint4*)&Bh[off] = uh;
        *(uint4*)&Bl[off] = ul;
    }
}

// ---------------- HMMA bf16-split GEMM, cp.async double-buffer + ldmatrix ----------------
// A planes [M][K], B planes [N][K]. MODE 0: C=AB  1: planes=gelu(AB+bias)
// 2: C=AB+bias+R (+optional planes)  3: C=AB+R
template<int MODE>
__global__ void __launch_bounds__(256) gemm_tc(
    const uint16_t* __restrict__ Ah, const uint16_t* __restrict__ Al,
    const uint16_t* __restrict__ Bh, const uint16_t* __restrict__ Bl,
    const float* __restrict__ bias, const float* __restrict__ R,
    float* __restrict__ C, uint16_t* __restrict__ Ch, uint16_t* __restrict__ Cl,
    int N, int K)
{
    extern __shared__ char sm[];
    const uint32_t sbase = (uint32_t)__cvta_generic_to_shared(sm);
    const int tid = threadIdx.x;
    const int warp = tid >> 5, lane = tid & 31;
    const int wm = warp & 1, wn = warp >> 1;
    const int m0 = blockIdx.y * 128, n0 = blockIdx.x * 128;
    const int KT = K >> 5;

    const uint16_t* gA[2] = { Ah + (size_t)m0 * K, Al + (size_t)m0 * K };
    const uint16_t* gB[2] = { Bh + (size_t)n0 * K, Bl + (size_t)n0 * K };

    // ldmatrix lane address components
    const int rl = lane & 7, grp = lane >> 3;
    const int a_r = rl + (grp & 1) * 8;          // + wm*64 + mt*16
    const int a_c = (grp >> 1) * 8;              // + kk
    const int b_r = rl + ((grp >> 1) & 1) * 8;   // + wn*32 + ntp*16
    const int b_c = (grp & 1) * 8;               // + kk

    float acc[4][4][4];
#pragma unroll
    for (int i = 0; i < 4; i++)
#pragma unroll
        for (int j = 0; j < 4; j++)
#pragma unroll
            for (int k = 0; k < 4; k++) acc[i][j][k] = 0.f;

    auto issue = [&](int stage, int kt) {
        uint32_t s0 = sbase + stage * STAGE_B;
        int kel = kt * 32;
#pragma unroll
        for (int pl = 0; pl < 4; pl++) {
            const uint16_t* g = (pl < 2) ? gA[pl] : gB[pl - 2];
#pragma unroll
            for (int i = 0; i < 2; i++) {
                int seg = tid + i * 256;
                int m = seg >> 2, s = seg & 3;
                cpa16(s0 + pl * PLANE_B + m * ROWB + s * 16,
                      g + (size_t)m * K + kel + s * 8);
            }
        }
        cpa_commit();
    };

    issue(0, 0);
    for (int kt = 0; kt < KT; kt++) {
        int st = kt & 1;
        if (kt + 1 < KT) { issue(st ^ 1, kt + 1); cpa_wait<1>(); }
        else             { cpa_wait<0>(); }
        __syncthreads();

        uint32_t sA_h = sbase + st * STAGE_B;
        uint32_t sA_l = sA_h + PLANE_B;
        uint32_t sB_h = sA_h + 2 * PLANE_B;
        uint32_t sB_l = sA_h + 3 * PLANE_B;

#pragma unroll
        for (int ks = 0; ks < 2; ks++) {
            const int kk = ks * 16;
            uint32_t bh[2][4], bl[2][4];
#pragma unroll
            for (int ntp = 0; ntp < 2; ntp++) {
                uint32_t off = (uint32_t)((wn * 32 + ntp * 16 + b_r) * ROWB + (kk + b_c) * 2);
                ldsm4(bh[ntp][0], bh[ntp][1], bh[ntp][2], bh[ntp][3], sB_h + off);
                ldsm4(bl[ntp][0], bl[ntp][1], bl[ntp][2], bl[ntp][3], sB_l + off);
            }
#pragma unroll
            for (int mt = 0; mt < 4; mt++) {
                uint32_t off = (uint32_t)((wm * 64 + mt * 16 + a_r) * ROWB + (kk + a_c) * 2);
                uint32_t ah[4], al[4];
                ldsm4(ah[0], ah[1], ah[2], ah[3], sA_h + off);
                ldsm4(al[0], al[1], al[2], al[3], sA_l + off);
#pragma unroll
                for (int nt = 0; nt < 4; nt++) {
                    uint32_t bfh[2] = { bh[nt >> 1][(nt & 1) * 2], bh[nt >> 1][(nt & 1) * 2 + 1] };
                    uint32_t bfl[2] = { bl[nt >> 1][(nt & 1) * 2], bl[nt >> 1][(nt & 1) * 2 + 1] };
                    mma16816(acc[mt][nt], ah, bfh);
                    mma16816(acc[mt][nt], ah, bfl);
                    mma16816(acc[mt][nt], al, bfh);
                }
            }
        }
        __syncthreads();
    }

    // epilogue
    const int r = lane >> 2, q = lane & 3;
#pragma unroll
    for (int mt = 0; mt < 4; mt++) {
#pragma unroll
        for (int nt = 0; nt < 4; nt++) {
            int row = m0 + wm * 64 + mt * 16 + r;
            int col = n0 + wn * 32 + nt * 8 + q * 2;
#pragma unroll
            for (int half = 0; half < 2; half++) {
                int rr2 = row + half * 8;
                float v0 = acc[mt][nt][half * 2 + 0];
                float v1 = acc[mt][nt][half * 2 + 1];
                size_t gidx = (size_t)rr2 * N + col;
                if (MODE == 1) {
                    v0 += bias[col];
                    v1 += bias[col + 1];
                    v0 = 0.5f * v0 * (1.0f + erff(v0 * 0.70710678118654752f));
                    v1 = 0.5f * v1 * (1.0f + erff(v1 * 0.70710678118654752f));
                    __nv_bfloat16 h0, h1, l0, l1;
                    split1(v0, h0, l0); split1(v1, h1, l1);
                    *(uint32_t*)&Ch[gidx] = pk2(h0, h1);
                    *(uint32_t*)&Cl[gidx] = pk2(l0, l1);
                } else {
                    if (MODE == 2) {
                        float2 rv = *(const float2*)&R[gidx];
                        v0 += bias[col] + rv.x;
                        v1 += bias[col + 1] + rv.y;
                    } else if (MODE == 3) {
                        float2 rv = *(const float2*)&R[gidx];
                        v0 += rv.x;
                        v1 += rv.y;
                    }
                    *(float2*)&C[gidx] = make_float2(v0, v1);
                    if (MODE == 2 && Ch) {
                        __nv_bfloat16 h0, h1, l0, l1;
                        split1(v0, h0, l0); split1(v1, h1, l1);
                        *(uint32_t*)&Ch[gidx] = pk2(h0, h1);
                        *(uint32_t*)&Cl[gidx] = pk2(l0, l1);
                    }
                }
            }
        }
    }
}

// ---------------- RoPE ----------------
__global__ void rope_kernel(float* __restrict__ x) {
    int idx = blockIdx.x * blockDim.x + threadIdx.x;
    int pc = idx & 255;
    int token = idx >> 8;
    int i = pc & 31;
    int s = token & (SS - 1);
    float inv = __expf(-logf(10000.0f) * ((float)i / 32.0f));
    float ang = (float)s * inv;
    float c = cosf(ang), sn = sinf(ang);
    float* p = x + (size_t)token * DAA + 2 * pc;
    float x1 = p[0], x2 = p[1];
    p[0] = x1 * c - x2 * sn;
    p[1] = x1 * sn + x2 * c;
}

// ---------------- Flash attention (fp32) -> bf16 hi/lo output planes ----------------
__global__ void __launch_bounds__(256) flash_kernel(
    const float* __restrict__ Qm, const float* __restrict__ Km,
    const float* __restrict__ Vm,
    __nv_bfloat16* __restrict__ Oh, __nv_bfloat16* __restrict__ Ol, int icl_mode)
{
    __shared__ float Qs[64][64];
    __shared__ float Kt[64][33];
    __shared__ float Vs[32][68];
    __shared__ float Ps[64][32];

    const int qt = blockIdx.x;
    const int bh = blockIdx.y;
    const int b = bh / HH, h = bh % HH;
    const int tid = threadIdx.x;
    const int warp = tid >> 5, lane = tid & 31;
    const int qg0 = qt * 64;
    const int r0 = warp * 8;

    const float* Qb = Qm + (size_t)b * SS * DAA + h * DHH;
    const float* Kb = Km + (size_t)b * SS * DAA + h * DHH;
    const float* Vb = Vm + (size_t)b * SS * DAA + h * DHH;

    for (int i = tid; i < 64 * 16; i += 256) {
        int r = i >> 4, c4 = i & 15;
        *(float4*)&Qs[r][c4 * 4] = *(const float4*)&Qb[(size_t)(qg0 + r) * DAA + c4 * 4];
    }

    float m[8], lsum[8], o0[8], o1[8];
#pragma unroll
    for (int r = 0; r < 8; r++) { m[r] = -1e30f; lsum[r] = 0.f; o0[r] = 0.f; o1[r] = 0.f; }

    const int ktmax = (qg0 + 63) >> 5;
    for (int kt = 0; kt <= ktmax; kt++) {
        const int kg0 = kt * 32;
        __syncthreads();
        for (int i = tid; i < 32 * 16; i += 256) {
            int c = i >> 4, d4 = i & 15;
            float4 k4 = *(const float4*)&Kb[(size_t)(kg0 + c) * DAA + d4 * 4];
            Kt[d4 * 4 + 0][c] = k4.x;
            Kt[d4 * 4 + 1][c] = k4.y;
            Kt[d4 * 4 + 2][c] = k4.z;
            Kt[d4 * 4 + 3][c] = k4.w;
            *(float4*)&Vs[c][d4 * 4] = *(const float4*)&Vb[(size_t)(kg0 + c) * DAA + d4 * 4];
        }
        __syncthreads();

        float sc[8];
#pragma unroll
        for (int r = 0; r < 8; r++) sc[r] = 0.f;
#pragma unroll
        for (int d4 = 0; d4 < 16; d4++) {
            float k0 = Kt[d4 * 4 + 0][lane];
            float k1 = Kt[d4 * 4 + 1][lane];
            float k2 = Kt[d4 * 4 + 2][lane];
            float k3 = Kt[d4 * 4 + 3][lane];
#pragma unroll
            for (int r = 0; r < 8; r++) {
                float4 q4 = *(float4*)&Qs[r0 + r][d4 * 4];
                sc[r] += q4.x * k0 + q4.y * k1 + q4.z * k2 + q4.w * k3;
            }
        }
        const int kg = kg0 + lane;
#pragma unroll
        for (int r = 0; r < 8; r++) {
            int qg = qg0 + r0 + r;
            bool allow = icl_mode ? (kg < qg || (qg == 0 && kg == 0)) : (kg <= qg);
            float s = allow ? sc[r] * SCALE_ATTN : -1e30f;
            float mx = s;
#pragma unroll
            for (int o = 16; o > 0; o >>= 1) mx = fmaxf(mx, __shfl_xor_sync(0xffffffffu, mx, o));
            float mnew = fmaxf(m[r], mx);
            float p = expf(s - mnew);
            float rs = p;
#pragma unroll
            for (int o = 16; o > 0; o >>= 1) rs += __shfl_xor_sync(0xffffffffu, rs, o);
            float corr = expf(m[r] - mnew);
            lsum[r] = lsum[r] * corr + rs;
            o0[r] *= corr; o1[r] *= corr;
            m[r] = mnew;
            Ps[r0 + r][lane] = p;
        }
        __syncwarp();
#pragma unroll
        for (int t = 0; t < 32; t++) {
            float va = Vs[t][lane];
            float vb = Vs[t][lane + 32];
#pragma unroll
            for (int r = 0; r < 8; r++) {
                float p = Ps[r0 + r][t];
                o0[r] += p * va;
                o1[r] += p * vb;
            }
        }
    }

    const size_t obase = (size_t)b * SS * DAA + h * DHH;
#pragma unroll
    for (int r = 0; r < 8; r++) {
        float inv = 1.0f / lsum[r];
        size_t off = obase + (size_t)(qg0 + r0 + r) * DAA;
        float va = o0[r] * inv, vb = o1[r] * inv;
        __nv_bfloat16 ha, la, hb, lb;
        split1(va, ha, la); split1(vb, hb, lb);
        Oh[off + lane] = ha;      Ol[off + lane] = la;
        Oh[off + lane + 32] = hb; Ol[off + lane + 32] = lb;
    }
}

// ---------------- host driver ----------------
#define GETSYM(T, var, sym) T* var; { void* _p; cudaGetSymbolAddress(&_p, sym); var = (T*)_p; }

extern "C" void kernel_launch(void* const* d_in, const int* in_sizes, int n_in,
                              void* d_out, int out_size)
{
    const float* cov_in  = (const float*)d_in[0];
    const float* tgt_in  = (const float*)d_in[1];
    const float* fu_in   = (const float*)d_in[2];
    const float* fc1w    = (const float*)d_in[3];
    const float* fc1b    = (const float*)d_in[4];
    const float* fc2w    = (const float*)d_in[5];
    const float* fc2b    = (const float*)d_in[6];
    const float* icl_wq  = (const float*)d_in[7];
    const float* icl_wk  = (const float*)d_in[8];
    const float* icl_wv  = (const float*)d_in[9];
    const float* icl_wo  = (const float*)d_in[10];
    const float* cov_wq  = (const float*)d_in[11];
    const float* cov_wk  = (const float*)d_in[12];
    const float* cov_wv  = (const float*)d_in[13];
    const float* cov_wo  = (const float*)d_in[14];
    const float* ln_cm_g = (const float*)d_in[15];
    const float* ln_cm_b = (const float*)d_in[16];
    const float* ln_ia_g = (const float*)d_in[17];
    const float* ln_ia_b = (const float*)d_in[18];
    const float* ln_im_g = (const float*)d_in[19];
    const float* ln_im_b = (const float*)d_in[20];

    float* out_cov = (float*)d_out;
    float* out_tgt = out_cov + (size_t)NTOK * EE;
    float* out_fu  = out_tgt + (size_t)NTOK * EE;

    GETSYM(float, qp, g_qp)  GETSYM(float, kp, g_kp)  GETSYM(float, vp, g_vp)
    GETSYM(uint16_t, lnh, pLNh)   GETSYM(uint16_t, lnl, pLNl)
    GETSYM(uint16_t, midh, pMIDh) GETSYM(uint16_t, midl, pMIDl)
    GETSYM(uint16_t, qh, pQh)     GETSYM(uint16_t, ql, pQl)
    GETSYM(uint16_t, tgh, pTGTh)  GETSYM(uint16_t, tgl, pTGTl)
    GETSYM(uint16_t, aoh, pAOh)   GETSYM(uint16_t, aol, pAOl)
    GETSYM(uint16_t, w1h, pW1h)   GETSYM(uint16_t, w1l, pW1l)
    GETSYM(uint16_t, w2h, pW2h)   GETSYM(uint16_t, w2l, pW2l)
    GETSYM(uint16_t, iqh, pIQh)   GETSYM(uint16_t, iql, pIQl)
    GETSYM(uint16_t, ikh, pIKh)   GETSYM(uint16_t, ikl, pIKl)
    GETSYM(uint16_t, ivh, pIVh)   GETSYM(uint16_t, ivl, pIVl)
    GETSYM(uint16_t, ioh, pIOh)   GETSYM(uint16_t, iol, pIOl)
    GETSYM(uint16_t, cqh, pCQh)   GETSYM(uint16_t, cql, pCQl)
    GETSYM(uint16_t, ckh, pCKh)   GETSYM(uint16_t, ckl, pCKl)
    GETSYM(uint16_t, cvh, pCVh)   GETSYM(uint16_t, cvl, pCVl)
    GETSYM(uint16_t, coh, pCOh)   GETSYM(uint16_t, col, pCOl)

    cudaFuncSetAttribute(gemm_tc<0>, cudaFuncAttributeMaxDynamicSharedMemorySize, SMEM_GEMM);
    cudaFuncSetAttribute(gemm_tc<1>, cudaFuncAttributeMaxDynamicSharedMemorySize, SMEM_GEMM);
    cudaFuncSetAttribute(gemm_tc<2>, cudaFuncAttributeMaxDynamicSharedMemorySize, SMEM_GEMM);
    cudaFuncSetAttribute(gemm_tc<3>, cudaFuncAttributeMaxDynamicSharedMemorySize, SMEM_GEMM);

    const dim3 thr(256);
    const dim3 gFC1(DMLP / 128, NTOK / 128);
    const dim3 gFC2(EE / 128, NTOK / 128);
    const dim3 gPRJ(DAA / 128, NTOK / 128);
    const dim3 gWO (EE / 128, NTOK / 128);
    const dim3 gFLASH(SS / 64, BB * HH);

    // weight conversions ([K,N] fp32 -> [N][K] bf16 hi/lo)
    convB<<<dim3(16, 16), thr>>>(fc1w, w1h, w1l, EE, DMLP);
    convB<<<dim3(8, 32),  thr>>>(fc2w, w2h, w2l, DMLP, EE);
    convB<<<dim3(4, 16), thr>>>(icl_wq, iqh, iql, EE, DAA);
    convB<<<dim3(4, 16), thr>>>(icl_wk, ikh, ikl, EE, DAA);
    convB<<<dim3(4, 16), thr>>>(icl_wv, ivh, ivl, EE, DAA);
    convB<<<dim3(8, 8),  thr>>>(icl_wo, ioh, iol, DAA, EE);
    convB<<<dim3(4, 16), thr>>>(cov_wq, cqh, cql, EE, DAA);
    convB<<<dim3(4, 16), thr>>>(cov_wk, ckh, ckl, EE, DAA);
    convB<<<dim3(4, 16), thr>>>(cov_wv, cvh, cvl, EE, DAA);
    convB<<<dim3(8, 8),  thr>>>(cov_wo, coh, col, DAA, EE);

    // cov = covariates + MLP(LN(covariates))
    ln_split<<<NTOK, thr>>>(cov_in, ln_cm_g, ln_cm_b, lnh, lnl);
    gemm_tc<1><<<gFC1, thr, SMEM_GEMM>>>(lnh, lnl, w1h, w1l, fc1b, nullptr,
                                         nullptr, midh, midl, DMLP, EE);
    gemm_tc<2><<<gFC2, thr, SMEM_GEMM>>>(midh, midl, w2h, w2l, fc2b, cov_in,
                                         out_cov, nullptr, nullptr, EE, DMLP);

    // tgt = targets + MLP(LN(functional_update))   (also emit tgt planes)
    ln_split<<<NTOK, thr>>>(fu_in, ln_im_g, ln_im_b, lnh, lnl);
    gemm_tc<1><<<gFC1, thr, SMEM_GEMM>>>(lnh, lnl, w1h, w1l, fc1b, nullptr,
                                         nullptr, midh, midl, DMLP, EE);
    gemm_tc<2><<<gFC2, thr, SMEM_GEMM>>>(midh, midl, w2h, w2l, fc2b, tgt_in,
                                         out_tgt, tgh, tgl, EE, DMLP);

    // q = LN(cov) planes
    ln_split<<<NTOK, thr>>>(out_cov, ln_ia_g, ln_ia_b, qh, ql);

    // ICL attention: fu = functional_update + attn(q, q, tgt)
    gemm_tc<0><<<gPRJ, thr, SMEM_GEMM>>>(qh, ql, iqh, iql, nullptr, nullptr,
                                         qp, nullptr, nullptr, DAA, EE);
    gemm_tc<0><<<gPRJ, thr, SMEM_GEMM>>>(qh, ql, ikh, ikl, nullptr, nullptr,
                                         kp, nullptr, nullptr, DAA, EE);
    gemm_tc<0><<<gPRJ, thr, SMEM_GEMM>>>(tgh, tgl, ivh, ivl, nullptr, nullptr,
                                         vp, nullptr, nullptr, DAA, EE);
    rope_kernel<<<NTOK, thr>>>(qp);
    rope_kernel<<<NTOK, thr>>>(kp);
    flash_kernel<<<gFLASH, thr>>>(qp, kp, vp, (__nv_bfloat16*)aoh, (__nv_bfloat16*)aol, 1);
    gemm_tc<3><<<gWO, thr, SMEM_GEMM>>>(aoh, aol, ioh, iol, nullptr, fu_in,
                                        out_fu, nullptr, nullptr, EE, DAA);

    // COV attention: cov = cov + attn(q, q, q)
    gemm_tc<0><<<gPRJ, thr, SMEM_GEMM>>>(qh, ql, cqh, cql, nullptr, nullptr,
                                         qp, nullptr, nullptr, DAA, EE);
    gemm_tc<0><<<gPRJ, thr, SMEM_GEMM>>>(qh, ql, ckh, ckl, nullptr, nullptr,
                                         kp, nullptr, nullptr, DAA, EE);
    gemm_tc<0><<<gPRJ, thr, SMEM_GEMM>>>(qh, ql, cvh, cvl, nullptr, nullptr,
                                         vp, nullptr, nullptr, DAA, EE);
    rope_kernel<<<NTOK, thr>>>(qp);
    rope_kernel<<<NTOK, thr>>>(kp);
    flash_kernel<<<gFLASH, thr>>>(qp, kp, vp, (__nv_bfloat16*)aoh, (__nv_bfloat16*)aol, 0);
    gemm_tc<3><<<gWO, thr, SMEM_GEMM>>>(aoh, aol, coh, col, nullptr, out_cov,
                                        out_cov, nullptr, nullptr, EE, DAA);
}

// round 5
// speedup vs baseline: 2.9790x; 1.6528x over previous
#include <cuda_runtime.h>
#include <cuda_bf16.h>
#include <math.h>
#include <stdint.h>

#define BB 2
#define SS 2048
#define EE 1024
#define HH 8
#define DHH 64
#define DAA 512
#define DMLP 2048
#define NTOK 4096
#define SCALE_ATTN 0.04419417382415922f
#define SCALE_L2E 0.06375944628228341f   // SCALE_ATTN * log2(e)
#define LN_EPS 1e-5f

// GEMM smem: per stage, 4 planes of 128 rows x 32 bf16, row stride 40 bf16 (80B)
#define ROWB 80
#define PLANE_B 10240
#define STAGE_B 40960
#define SMEM_GEMM (2 * STAGE_B)

// Flash smem: Q hi/lo [128][72], stages {Kh,Kl,Vh,Vl}[64][72] x2
#define FROWB 144
#define FQPL 18432           // 128*144
#define FKPL 9216            // 64*144
#define FSTG 36864           // 4 planes
#define SMEM_FLASH (2 * FQPL + 2 * FSTG)   // 110592

// ---------------- fp32 scratch ----------------
__device__ float g_qkv[NTOK * 1536];

// ---------------- bf16 hi/lo planes ----------------
__device__ uint16_t pLNh[NTOK * EE],    pLNl[NTOK * EE];
__device__ uint16_t pMIDh[NTOK * DMLP], pMIDl[NTOK * DMLP];
__device__ uint16_t pQh[NTOK * EE],     pQl[NTOK * EE];
__device__ uint16_t pTGTh[NTOK * EE],   pTGTl[NTOK * EE];
__device__ uint16_t pAOh[NTOK * DAA],   pAOl[NTOK * DAA];
__device__ uint16_t pFQh[NTOK * DAA],   pFQl[NTOK * DAA];
__device__ uint16_t pFKh[NTOK * DAA],   pFKl[NTOK * DAA];
__device__ uint16_t pFVh[NTOK * DAA],   pFVl[NTOK * DAA];

__device__ uint16_t pW1h[DMLP * EE],    pW1l[DMLP * EE];
__device__ uint16_t pW2h[EE * DMLP],    pW2l[EE * DMLP];
__device__ uint16_t pIQKh[1024 * EE],   pIQKl[1024 * EE];     // [wq|wk] rows
__device__ uint16_t pIVh[DAA * EE],     pIVl[DAA * EE];
__device__ uint16_t pIOh[EE * DAA],     pIOl[EE * DAA];
__device__ uint16_t pCQKVh[1536 * EE],  pCQKVl[1536 * EE];    // [wq|wk|wv]
__device__ uint16_t pCOh[EE * DAA],     pCOl[EE * DAA];

// ---------------- helpers ----------------
__device__ __forceinline__ uint32_t pk2(__nv_bfloat16 a, __nv_bfloat16 b) {
    uint16_t ra = *reinterpret_cast<uint16_t*>(&a);
    uint16_t rb = *reinterpret_cast<uint16_t*>(&b);
    return (uint32_t)ra | ((uint32_t)rb << 16);
}
__device__ __forceinline__ void split1(float x, __nv_bfloat16& h, __nv_bfloat16& l) {
    h = __float2bfloat16(x);
    l = __float2bfloat16(x - __bfloat162float(h));
}
__device__ __forceinline__ void mma16816(float* c, const uint32_t* a, const uint32_t* b) {
    asm volatile(
        "mma.sync.aligned.m16n8k16.row.col.f32.bf16.bf16.f32 "
        "{%0,%1,%2,%3}, {%4,%5,%6,%7}, {%8,%9}, {%0,%1,%2,%3};"
        : "+f"(c[0]), "+f"(c[1]), "+f"(c[2]), "+f"(c[3])
        : "r"(a[0]), "r"(a[1]), "r"(a[2]), "r"(a[3]), "r"(b[0]), "r"(b[1]));
}
__device__ __forceinline__ void ldsm4(uint32_t& r0, uint32_t& r1, uint32_t& r2, uint32_t& r3,
                                      uint32_t addr) {
    asm volatile("ldmatrix.sync.aligned.m8n8.x4.shared.b16 {%0,%1,%2,%3}, [%4];"
                 : "=r"(r0), "=r"(r1), "=r"(r2), "=r"(r3) : "r"(addr));
}
__device__ __forceinline__ void ldsm4t(uint32_t& r0, uint32_t& r1, uint32_t& r2, uint32_t& r3,
                                       uint32_t addr) {
    asm volatile("ldmatrix.sync.aligned.m8n8.x4.trans.shared.b16 {%0,%1,%2,%3}, [%4];"
                 : "=r"(r0), "=r"(r1), "=r"(r2), "=r"(r3) : "r"(addr));
}
__device__ __forceinline__ void cpa16(uint32_t s, const void* g) {
    asm volatile("cp.async.ca.shared.global [%0], [%1], 16;" :: "r"(s), "l"(g));
}
__device__ __forceinline__ void cpa_commit() {
    asm volatile("cp.async.commit_group;" ::: "memory");
}
template<int N>
__device__ __forceinline__ void cpa_wait() {
    asm volatile("cp.async.wait_group %0;" :: "n"(N) : "memory");
}
// exp2 via degree-5 polynomial on [-0.5, 0.5] (max err ~1.7e-6); no MUFU.
__device__ __forceinline__ float exp2p(float x) {
    x = fmaxf(x, -80.f);
    float n = rintf(x);
    float f = x - n;
    float p = 1.3333558146428443e-3f;
    p = p * f + 9.618129107628477e-3f;
    p = p * f + 5.550410866482158e-2f;
    p = p * f + 2.402265069591007e-1f;
    p = p * f + 6.931471805599453e-1f;
    p = p * f + 1.0f;
    return p * __int_as_float(((int)n + 127) << 23);
}

__device__ __forceinline__ float block_reduce_sum(float v) {
    __shared__ float red[32];
    int lane = threadIdx.x & 31, w = threadIdx.x >> 5;
#pragma unroll
    for (int o = 16; o > 0; o >>= 1) v += __shfl_xor_sync(0xffffffffu, v, o);
    __syncthreads();
    if (lane == 0) red[w] = v;
    __syncthreads();
    v = (lane < 8) ? red[lane] : 0.f;
#pragma unroll
    for (int o = 16; o > 0; o >>= 1) v += __shfl_xor_sync(0xffffffffu, v, o);
    return v;
}

// ---------------- LayerNorm -> bf16 hi/lo planes ----------------
__global__ void ln_split(const float* __restrict__ x, const float* __restrict__ g,
                         const float* __restrict__ b,
                         uint16_t* __restrict__ oh, uint16_t* __restrict__ ol) {
    int row = blockIdx.x, t = threadIdx.x;
    float4 v = *(const float4*)&x[(size_t)row * EE + 4 * t];
    float s = v.x + v.y + v.z + v.w;
    float mean = block_reduce_sum(s) * (1.0f / EE);
    float d0 = v.x - mean, d1 = v.y - mean, d2 = v.z - mean, d3 = v.w - mean;
    float var = block_reduce_sum(d0 * d0 + d1 * d1 + d2 * d2 + d3 * d3) * (1.0f / EE);
    float rstd = rsqrtf(var + LN_EPS);
    float4 gg = *(const float4*)&g[4 * t];
    float4 bb = *(const float4*)&b[4 * t];
    float y0 = d0 * rstd * gg.x + bb.x;
    float y1 = d1 * rstd * gg.y + bb.y;
    float y2 = d2 * rstd * gg.z + bb.z;
    float y3 = d3 * rstd * gg.w + bb.w;
    __nv_bfloat16 h0, h1, h2, h3, l0, l1, l2, l3;
    split1(y0, h0, l0); split1(y1, h1, l1); split1(y2, h2, l2); split1(y3, h3, l3);
    size_t off = (size_t)row * EE + 4 * t;
    *(uint2*)&oh[off] = make_uint2(pk2(h0, h1), pk2(h2, h3));
    *(uint2*)&ol[off] = make_uint2(pk2(l0, l1), pk2(l2, l3));
}

// ---------------- weight fp32 [K,N] -> planes [N][K], batched ----------------
struct CB6 { const float* s[6]; uint16_t* dh[6]; uint16_t* dl[6]; };

__device__ __forceinline__ void convB_body(const float* __restrict__ W,
                                           uint16_t* __restrict__ Bh,
                                           uint16_t* __restrict__ Bl, int K, int N) {
    __shared__ float ts[64][129];
    int nt = blockIdx.x, kt = blockIdx.y, tid = threadIdx.x;
    int k0 = kt * 64, n0 = nt * 128;
#pragma unroll
    for (int i = 0; i < 32; i++) {
        int idx = tid + i * 256;
        int kk = idx >> 7, nn = idx & 127;
        ts[kk][nn] = W[(size_t)(k0 + kk) * N + n0 + nn];
    }
    __syncthreads();
#pragma unroll
    for (int j = 0; j < 4; j++) {
        int job = tid + j * 256;
        int n = job >> 3, kg = (job & 7) * 8;
        __nv_bfloat16 h[8], l[8];
#pragma unroll
        for (int i = 0; i < 8; i++) split1(ts[kg + i][n], h[i], l[i]);
        uint4 uh = make_uint4(pk2(h[0], h[1]), pk2(h[2], h[3]), pk2(h[4], h[5]), pk2(h[6], h[7]));
        uint4 ul = make_uint4(pk2(l[0], l[1]), pk2(l[2], l[3]), pk2(l[4], l[5]), pk2(l[6], l[7]));
        size_t off = (size_t)(n0 + n) * K + k0 + kg;
        *(uint4*)&Bh[off] = uh;
        *(uint4*)&Bl[off] = ul;
    }
}
__global__ void convB(const float* __restrict__ W, uint16_t* __restrict__ Bh,
                      uint16_t* __restrict__ Bl, int K, int N) {
    convB_body(W, Bh, Bl, K, N);
}
__global__ void convB_batch(CB6 a, int K, int N) {
    int w = blockIdx.z;
    convB_body(a.s[w], a.dh[w], a.dl[w], K, N);
}

// ---------------- HMMA bf16-split GEMM ----------------
// MODE 0: C=AB(fp32, ldC)  1: planes=gelu(AB+bias)  2: C=AB+bias+R (+planes)  3: C=AB+R
template<int MODE>
__global__ void __launch_bounds__(256) gemm_tc(
    const uint16_t* __restrict__ Ah, const uint16_t* __restrict__ Al,
    const uint16_t* __restrict__ Bh, const uint16_t* __restrict__ Bl,
    const float* __restrict__ bias, const float* __restrict__ R,
    float* __restrict__ C, uint16_t* __restrict__ Ch, uint16_t* __restrict__ Cl,
    int N, int K, int ldC)
{
    extern __shared__ char sm[];
    const uint32_t sbase = (uint32_t)__cvta_generic_to_shared(sm);
    const int tid = threadIdx.x;
    const int warp = tid >> 5, lane = tid & 31;
    const int wm = warp & 1, wn = warp >> 1;
    const int m0 = blockIdx.y * 128, n0 = blockIdx.x * 128;
    const int KT = K >> 5;

    const uint16_t* gA[2] = { Ah + (size_t)m0 * K, Al + (size_t)m0 * K };
    const uint16_t* gB[2] = { Bh + (size_t)n0 * K, Bl + (size_t)n0 * K };

    const int rl = lane & 7, grp = lane >> 3;
    const int a_r = rl + (grp & 1) * 8;
    const int a_c = (grp >> 1) * 8;
    const int b_r = rl + ((grp >> 1) & 1) * 8;
    const int b_c = (grp & 1) * 8;

    float acc[4][4][4];
#pragma unroll
    for (int i = 0; i < 4; i++)
#pragma unroll
        for (int j = 0; j < 4; j++)
#pragma unroll
            for (int k = 0; k < 4; k++) acc[i][j][k] = 0.f;

    auto issue = [&](int stage, int kt) {
        uint32_t s0 = sbase + stage * STAGE_B;
        int kel = kt * 32;
#pragma unroll
        for (int pl = 0; pl < 4; pl++) {
            const uint16_t* g = (pl < 2) ? gA[pl] : gB[pl - 2];
#pragma unroll
            for (int i = 0; i < 2; i++) {
                int seg = tid + i * 256;
                int m = seg >> 2, s = seg & 3;
                cpa16(s0 + pl * PLANE_B + m * ROWB + s * 16,
                      g + (size_t)m * K + kel + s * 8);
            }
        }
        cpa_commit();
    };

    issue(0, 0);
    for (int kt = 0; kt < KT; kt++) {
        int st = kt & 1;
        if (kt + 1 < KT) { issue(st ^ 1, kt + 1); cpa_wait<1>(); }
        else             { cpa_wait<0>(); }
        __syncthreads();

        uint32_t sA_h = sbase + st * STAGE_B;
        uint32_t sA_l = sA_h + PLANE_B;
        uint32_t sB_h = sA_h + 2 * PLANE_B;
        uint32_t sB_l = sA_h + 3 * PLANE_B;

#pragma unroll
        for (int ks = 0; ks < 2; ks++) {
            const int kk = ks * 16;
            uint32_t bh[2][4], bl[2][4];
#pragma unroll
            for (int ntp = 0; ntp < 2; ntp++) {
                uint32_t off = (uint32_t)((wn * 32 + ntp * 16 + b_r) * ROWB + (kk + b_c) * 2);
                ldsm4(bh[ntp][0], bh[ntp][1], bh[ntp][2], bh[ntp][3], sB_h + off);
                ldsm4(bl[ntp][0], bl[ntp][1], bl[ntp][2], bl[ntp][3], sB_l + off);
            }
#pragma unroll
            for (int mt = 0; mt < 4; mt++) {
                uint32_t off = (uint32_t)((wm * 64 + mt * 16 + a_r) * ROWB + (kk + a_c) * 2);
                uint32_t ah[4], al[4];
                ldsm4(ah[0], ah[1], ah[2], ah[3], sA_h + off);
                ldsm4(al[0], al[1], al[2], al[3], sA_l + off);
#pragma unroll
                for (int nt = 0; nt < 4; nt++) {
                    uint32_t bfh[2] = { bh[nt >> 1][(nt & 1) * 2], bh[nt >> 1][(nt & 1) * 2 + 1] };
                    uint32_t bfl[2] = { bl[nt >> 1][(nt & 1) * 2], bl[nt >> 1][(nt & 1) * 2 + 1] };
                    mma16816(acc[mt][nt], ah, bfh);
                    mma16816(acc[mt][nt], ah, bfl);
                    mma16816(acc[mt][nt], al, bfh);
                }
            }
        }
        __syncthreads();
    }

    const int r = lane >> 2, q = lane & 3;
#pragma unroll
    for (int mt = 0; mt < 4; mt++) {
#pragma unroll
        for (int nt = 0; nt < 4; nt++) {
            int row = m0 + wm * 64 + mt * 16 + r;
            int col = n0 + wn * 32 + nt * 8 + q * 2;
#pragma unroll
            for (int half = 0; half < 2; half++) {
                int rr2 = row + half * 8;
                float v0 = acc[mt][nt][half * 2 + 0];
                float v1 = acc[mt][nt][half * 2 + 1];
                size_t gidx = (size_t)rr2 * ldC + col;
                if (MODE == 1) {
                    v0 += bias[col];
                    v1 += bias[col + 1];
                    v0 = 0.5f * v0 * (1.0f + erff(v0 * 0.70710678118654752f));
                    v1 = 0.5f * v1 * (1.0f + erff(v1 * 0.70710678118654752f));
                    __nv_bfloat16 h0, h1, l0, l1;
                    split1(v0, h0, l0); split1(v1, h1, l1);
                    *(uint32_t*)&Ch[gidx] = pk2(h0, h1);
                    *(uint32_t*)&Cl[gidx] = pk2(l0, l1);
                } else {
                    if (MODE == 2) {
                        float2 rv = *(const float2*)&R[gidx];
                        v0 += bias[col] + rv.x;
                        v1 += bias[col + 1] + rv.y;
                    } else if (MODE == 3) {
                        float2 rv = *(const float2*)&R[gidx];
                        v0 += rv.x;
                        v1 += rv.y;
                    }
                    *(float2*)&C[gidx] = make_float2(v0, v1);
                    if (MODE == 2 && Ch) {
                        __nv_bfloat16 h0, h1, l0, l1;
                        split1(v0, h0, l0); split1(v1, h1, l1);
                        *(uint32_t*)&Ch[gidx] = pk2(h0, h1);
                        *(uint32_t*)&Cl[gidx] = pk2(l0, l1);
                    }
                }
            }
        }
    }
}

// ---------------- RoPE on q,k + split q,k,v to bf16 planes ----------------
// qkv: [NTOK][1536] fp32 (q 0-511, k 512-1023, v 1024-1535)
__global__ void rope_split(const float* __restrict__ qkv,
                           uint16_t* __restrict__ fqh, uint16_t* __restrict__ fql,
                           uint16_t* __restrict__ fkh, uint16_t* __restrict__ fkl,
                           uint16_t* __restrict__ fvh, uint16_t* __restrict__ fvl) {
    int row = blockIdx.x, t = threadIdx.x;
    int i = t & 31;
    int s = row & (SS - 1);
    float inv = __expf(-logf(10000.0f) * ((float)i / 32.0f));
    float ang = (float)s * inv;
    float c = cosf(ang), sn = sinf(ang);
    const float* base = qkv + (size_t)row * 1536;
    size_t dst = (size_t)row * DAA + 2 * t;

    float x1 = base[2 * t], x2 = base[2 * t + 1];
    float o1 = x1 * c - x2 * sn, o2 = x1 * sn + x2 * c;
    __nv_bfloat16 h0, h1, l0, l1;
    split1(o1, h0, l0); split1(o2, h1, l1);
    *(uint32_t*)&fqh[dst] = pk2(h0, h1);
    *(uint32_t*)&fql[dst] = pk2(l0, l1);

    x1 = base[512 + 2 * t]; x2 = base[512 + 2 * t + 1];
    o1 = x1 * c - x2 * sn; o2 = x1 * sn + x2 * c;
    split1(o1, h0, l0); split1(o2, h1, l1);
    *(uint32_t*)&fkh[dst] = pk2(h0, h1);
    *(uint32_t*)&fkl[dst] = pk2(l0, l1);

    x1 = base[1024 + 2 * t]; x2 = base[1024 + 2 * t + 1];
    split1(x1, h0, l0); split1(x2, h1, l1);
    *(uint32_t*)&fvh[dst] = pk2(h0, h1);
    *(uint32_t*)&fvl[dst] = pk2(l0, l1);
}

// ---------------- Flash attention, HMMA + poly exp2 ----------------
// BQ=128 (8 warps x 16 rows), BK=64, DH=64. ICL=1: kg<qg plus (0,0). ICL=0: kg<=qg.
template<int ICL>
__global__ void __launch_bounds__(256) flash_mma(
    const uint16_t* __restrict__ Qh, const uint16_t* __restrict__ Ql,
    const uint16_t* __restrict__ Kh, const uint16_t* __restrict__ Kl,
    const uint16_t* __restrict__ Vh, const uint16_t* __restrict__ Vl,
    uint16_t* __restrict__ Oh, uint16_t* __restrict__ Ol)
{
    extern __shared__ char sm[];
    const uint32_t sb = (uint32_t)__cvta_generic_to_shared(sm);
    const uint32_t sQh = sb, sQl = sb + FQPL;
    const uint32_t sKV = sb + 2 * FQPL;
    const int tid = threadIdx.x, warp = tid >> 5, lane = tid & 31;
    const int qt = gridDim.x - 1 - blockIdx.x;
    const int bh = blockIdx.y, b = bh >> 3, h = bh & 7;
    const int qg0 = qt * 128;
    const size_t tokb = (size_t)b * SS;
    const int rb = warp * 16;

    const int rl = lane & 7, grp = lane >> 3;
    const int a_r = rl + (grp & 1) * 8;
    const int a_c = (grp >> 1) * 8;
    const int b_r = rl + ((grp >> 1) & 1) * 8;
    const int b_c = (grp & 1) * 8;

    // Q tile load (group 0)
#pragma unroll
    for (int i = 0; i < 8; i++) {
        int job = tid + i * 256;
        int pl = job >> 10, r = (job >> 3) & 127, s = job & 7;
        const uint16_t* g = (pl ? Ql : Qh) + (tokb + qg0 + r) * DAA + h * DHH + s * 8;
        cpa16((pl ? sQl : sQh) + r * FROWB + s * 16, g);
    }
    cpa_commit();

    float out[8][4];
#pragma unroll
    for (int i = 0; i < 8; i++)
#pragma unroll
        for (int j = 0; j < 4; j++) out[i][j] = 0.f;
    float mrow[2] = { -1e30f, -1e30f }, lrow[2] = { 0.f, 0.f };

    const int ktmax = (qg0 + 127) >> 6;

    auto issueKV = [&](int st, int kt) {
        uint32_t s0 = sKV + st * FSTG;
        int kg0 = kt * 64;
#pragma unroll
        for (int i = 0; i < 8; i++) {
            int job = tid + i * 256;
            int pl = job >> 9, r = (job >> 3) & 63, s = job & 7;
            const uint16_t* gp = (pl == 0) ? Kh : (pl == 1) ? Kl : (pl == 2) ? Vh : Vl;
            cpa16(s0 + pl * FKPL + r * FROWB + s * 16,
                  gp + (tokb + kg0 + r) * DAA + h * DHH + s * 8);
        }
        cpa_commit();
    };
    issueKV(0, 0);

    const int qrow0 = qg0 + rb + (lane >> 2);   // global q row for ri=0 (ri=1: +8)

    for (int kt = 0; kt <= ktmax; kt++) {
        int st = kt & 1;
        int kg0 = kt * 64;
        if (kt < ktmax) { issueKV(st ^ 1, kt + 1); cpa_wait<1>(); }
        else            { cpa_wait<0>(); }
        __syncthreads();

        uint32_t sK_h = sKV + st * FSTG;
        uint32_t sK_l = sK_h + FKPL;
        uint32_t sV_h = sK_h + 2 * FKPL;
        uint32_t sV_l = sK_h + 3 * FKPL;

        // S = Q K^T  (3-term hi/lo)
        float sc[8][4];
#pragma unroll
        for (int i = 0; i < 8; i++)
#pragma unroll
            for (int j = 0; j < 4; j++) sc[i][j] = 0.f;
#pragma unroll
        for (int k16 = 0; k16 < 4; k16++) {
            uint32_t qoff = (uint32_t)((rb + a_r) * FROWB + (k16 * 16 + a_c) * 2);
            uint32_t ah[4], al[4];
            ldsm4(ah[0], ah[1], ah[2], ah[3], sQh + qoff);
            ldsm4(al[0], al[1], al[2], al[3], sQl + qoff);
#pragma unroll
            for (int ntp = 0; ntp < 4; ntp++) {
                uint32_t koff = (uint32_t)((ntp * 16 + b_r) * FROWB + (k16 * 16 + b_c) * 2);
                uint32_t kh[4], kl[4];
                ldsm4(kh[0], kh[1], kh[2], kh[3], sK_h + koff);
                ldsm4(kl[0], kl[1], kl[2], kl[3], sK_l + koff);
#pragma unroll
                for (int u = 0; u < 2; u++) {
                    int nt = ntp * 2 + u;
                    uint32_t bfh[2] = { kh[u * 2], kh[u * 2 + 1] };
                    uint32_t bfl[2] = { kl[u * 2], kl[u * 2 + 1] };
                    mma16816(sc[nt], ah, bfh);
                    mma16816(sc[nt], ah, bfl);
                    mma16816(sc[nt], al, bfh);
                }
            }
        }

        // scale to log2 domain + mask
        const bool boundary = (kg0 + 63 >= qg0);
#pragma unroll
        for (int nt = 0; nt < 8; nt++) {
#pragma unroll
            for (int c = 0; c < 4; c++) {
                float v = sc[nt][c] * SCALE_L2E;
                if (boundary) {
                    int qg = qrow0 + (c >> 1) * 8;
                    int kg = kg0 + nt * 8 + (lane & 3) * 2 + (c & 1);
                    bool allow = ICL ? (kg < qg || (qg | kg) == 0) : (kg <= qg);
                    v = allow ? v : -1e30f;
                }
                sc[nt][c] = v;
            }
        }

        // online softmax (per ri row)
#pragma unroll
        for (int ri = 0; ri < 2; ri++) {
            float mx = -1e30f;
#pragma unroll
            for (int nt = 0; nt < 8; nt++)
                mx = fmaxf(mx, fmaxf(sc[nt][ri * 2], sc[nt][ri * 2 + 1]));
            mx = fmaxf(mx, __shfl_xor_sync(0xffffffffu, mx, 1));
            mx = fmaxf(mx, __shfl_xor_sync(0xffffffffu, mx, 2));
            float mn = fmaxf(mrow[ri], mx);
            float corr = exp2p(mrow[ri] - mn);
            mrow[ri] = mn;
            float rs = 0.f;
#pragma unroll
            for (int nt = 0; nt < 8; nt++) {
                float p0 = exp2p(sc[nt][ri * 2] - mn);
                float p1 = exp2p(sc[nt][ri * 2 + 1] - mn);
                sc[nt][ri * 2] = p0;
                sc[nt][ri * 2 + 1] = p1;
                rs += p0 + p1;
            }
            rs += __shfl_xor_sync(0xffffffffu, rs, 1);
            rs += __shfl_xor_sync(0xffffffffu, rs, 2);
            lrow[ri] = lrow[ri] * corr + rs;
#pragma unroll
            for (int nt = 0; nt < 8; nt++) {
                out[nt][ri * 2] *= corr;
                out[nt][ri * 2 + 1] *= corr;
            }
        }

        // PV: out += P V  (P bf16, V hi/lo)
#pragma unroll
        for (int j = 0; j < 4; j++) {
            __nv_bfloat16 bh0, bh1;
            uint32_t aP[4];
            split1(sc[2 * j][0], bh0, bh1);   // reuse split1 only for cvt? no — direct cvt:
            aP[0] = pk2(__float2bfloat16(sc[2 * j][0]),     __float2bfloat16(sc[2 * j][1]));
            aP[1] = pk2(__float2bfloat16(sc[2 * j][2]),     __float2bfloat16(sc[2 * j][3]));
            aP[2] = pk2(__float2bfloat16(sc[2 * j + 1][0]), __float2bfloat16(sc[2 * j + 1][1]));
            aP[3] = pk2(__float2bfloat16(sc[2 * j + 1][2]), __float2bfloat16(sc[2 * j + 1][3]));
#pragma unroll
            for (int nt2 = 0; nt2 < 4; nt2++) {
                // V trans: lane addr row = j*16 + (grp&1)*8 + rl, col = nt2*16 + (grp>>1)*8
                uint32_t voff = (uint32_t)((j * 16 + (grp & 1) * 8 + rl) * FROWB
                                           + (nt2 * 16 + (grp >> 1) * 8) * 2);
                uint32_t bv[4];
                ldsm4t(bv[0], bv[1], bv[2], bv[3], sV_h + voff);
                {
                    uint32_t b0[2] = { bv[0], bv[1] }, b1[2] = { bv[2], bv[3] };
                    mma16816(out[nt2 * 2], aP, b0);
                    mma16816(out[nt2 * 2 + 1], aP, b1);
                }
                ldsm4t(bv[0], bv[1], bv[2], bv[3], sV_l + voff);
                {
                    uint32_t b0[2] = { bv[0], bv[1] }, b1[2] = { bv[2], bv[3] };
                    mma16816(out[nt2 * 2], aP, b0);
                    mma16816(out[nt2 * 2 + 1], aP, b1);
                }
            }
        }
        __syncthreads();   // stage reuse guard
    }

    // write output planes
#pragma unroll
    for (int ri = 0; ri < 2; ri++) {
        float inv = 1.0f / lrow[ri];
        size_t rbase = (tokb + qrow0 + ri * 8) * DAA + h * DHH + (lane & 3) * 2;
#pragma unroll
        for (int nt = 0; nt < 8; nt++) {
            float v0 = out[nt][ri * 2] * inv;
            float v1 = out[nt][ri * 2 + 1] * inv;
            __nv_bfloat16 h0, h1, l0, l1;
            split1(v0, h0, l0); split1(v1, h1, l1);
            *(uint32_t*)&Oh[rbase + nt * 8] = pk2(h0, h1);
            *(uint32_t*)&Ol[rbase + nt * 8] = pk2(l0, l1);
        }
    }
}

// ---------------- host driver ----------------
#define GETSYM(T, var, sym) T* var; { void* _p; cudaGetSymbolAddress(&_p, sym); var = (T*)_p; }

extern "C" void kernel_launch(void* const* d_in, const int* in_sizes, int n_in,
                              void* d_out, int out_size)
{
    const float* cov_in  = (const float*)d_in[0];
    const float* tgt_in  = (const float*)d_in[1];
    const float* fu_in   = (const float*)d_in[2];
    const float* fc1w    = (const float*)d_in[3];
    const float* fc1b    = (const float*)d_in[4];
    const float* fc2w    = (const float*)d_in[5];
    const float* fc2b    = (const float*)d_in[6];
    const float* icl_wq  = (const float*)d_in[7];
    const float* icl_wk  = (const float*)d_in[8];
    const float* icl_wv  = (const float*)d_in[9];
    const float* icl_wo  = (const float*)d_in[10];
    const float* cov_wq  = (const float*)d_in[11];
    const float* cov_wk  = (const float*)d_in[12];
    const float* cov_wv  = (const float*)d_in[13];
    const float* cov_wo  = (const float*)d_in[14];
    const float* ln_cm_g = (const float*)d_in[15];
    const float* ln_cm_b = (const float*)d_in[16];
    const float* ln_ia_g = (const float*)d_in[17];
    const float* ln_ia_b = (const float*)d_in[18];
    const float* ln_im_g = (const float*)d_in[19];
    const float* ln_im_b = (const float*)d_in[20];

    float* out_cov = (float*)d_out;
    float* out_tgt = out_cov + (size_t)NTOK * EE;
    float* out_fu  = out_tgt + (size_t)NTOK * EE;

    GETSYM(float, qkv, g_qkv)
    GETSYM(uint16_t, lnh, pLNh)    GETSYM(uint16_t, lnl, pLNl)
    GETSYM(uint16_t, midh, pMIDh)  GETSYM(uint16_t, midl, pMIDl)
    GETSYM(uint16_t, qh, pQh)      GETSYM(uint16_t, ql, pQl)
    GETSYM(uint16_t, tgh, pTGTh)   GETSYM(uint16_t, tgl, pTGTl)
    GETSYM(uint16_t, aoh, pAOh)    GETSYM(uint16_t, aol, pAOl)
    GETSYM(uint16_t, fqh, pFQh)    GETSYM(uint16_t, fql, pFQl)
    GETSYM(uint16_t, fkh, pFKh)    GETSYM(uint16_t, fkl, pFKl)
    GETSYM(uint16_t, fvh, pFVh)    GETSYM(uint16_t, fvl, pFVl)
    GETSYM(uint16_t, w1h, pW1h)    GETSYM(uint16_t, w1l, pW1l)
    GETSYM(uint16_t, w2h, pW2h)    GETSYM(uint16_t, w2l, pW2l)
    GETSYM(uint16_t, iqkh, pIQKh)  GETSYM(uint16_t, iqkl, pIQKl)
    GETSYM(uint16_t, ivh, pIVh)    GETSYM(uint16_t, ivl, pIVl)
    GETSYM(uint16_t, ioh, pIOh)    GETSYM(uint16_t, iol, pIOl)
    GETSYM(uint16_t, cqkvh, pCQKVh) GETSYM(uint16_t, cqkvl, pCQKVl)
    GETSYM(uint16_t, coh, pCOh)    GETSYM(uint16_t, col, pCOl)

    cudaFuncSetAttribute(gemm_tc<0>, cudaFuncAttributeMaxDynamicSharedMemorySize, SMEM_GEMM);
    cudaFuncSetAttribute(gemm_tc<1>, cudaFuncAttributeMaxDynamicSharedMemorySize, SMEM_GEMM);
    cudaFuncSetAttribute(gemm_tc<2>, cudaFuncAttributeMaxDynamicSharedMemorySize, SMEM_GEMM);
    cudaFuncSetAttribute(gemm_tc<3>, cudaFuncAttributeMaxDynamicSharedMemorySize, SMEM_GEMM);
    cudaFuncSetAttribute(flash_mma<0>, cudaFuncAttributeMaxDynamicSharedMemorySize, SMEM_FLASH);
    cudaFuncSetAttribute(flash_mma<1>, cudaFuncAttributeMaxDynamicSharedMemorySize, SMEM_FLASH);

    const dim3 thr(256);
    const dim3 gFC1(DMLP / 128, NTOK / 128);
    const dim3 gFC2(EE / 128, NTOK / 128);
    const dim3 gQK(8, NTOK / 128);
    const dim3 gV(4, NTOK / 128);
    const dim3 gQKV(12, NTOK / 128);
    const dim3 gWO(EE / 128, NTOK / 128);
    const dim3 gFLASH(SS / 128, BB * HH);

    // ---- weight conversions (3 launches) ----
    CB6 c6;
    c6.s[0] = icl_wq; c6.dh[0] = iqkh;               c6.dl[0] = iqkl;
    c6.s[1] = icl_wk; c6.dh[1] = iqkh + 512 * EE;    c6.dl[1] = iqkl + 512 * EE;
    c6.s[2] = icl_wv; c6.dh[2] = ivh;                c6.dl[2] = ivl;
    c6.s[3] = cov_wq; c6.dh[3] = cqkvh;              c6.dl[3] = cqkvl;
    c6.s[4] = cov_wk; c6.dh[4] = cqkvh + 512 * EE;   c6.dl[4] = cqkvl + 512 * EE;
    c6.s[5] = cov_wv; c6.dh[5] = cqkvh + 1024 * EE;  c6.dl[5] = cqkvl + 1024 * EE;
    convB_batch<<<dim3(4, 16, 6), thr>>>(c6, EE, DAA);
    CB6 c2;
    c2.s[0] = icl_wo; c2.dh[0] = ioh; c2.dl[0] = iol;
    c2.s[1] = cov_wo; c2.dh[1] = coh; c2.dl[1] = col;
    convB_batch<<<dim3(8, 8, 2), thr>>>(c2, DAA, EE);
    convB<<<dim3(16, 16), thr>>>(fc1w, w1h, w1l, EE, DMLP);
    convB<<<dim3(8, 32), thr>>>(fc2w, w2h, w2l, DMLP, EE);

    // ---- cov = covariates + MLP(LN(covariates)) ----
    ln_split<<<NTOK, thr>>>(cov_in, ln_cm_g, ln_cm_b, lnh, lnl);
    gemm_tc<1><<<gFC1, thr, SMEM_GEMM>>>(lnh, lnl, w1h, w1l, fc1b, nullptr,
                                         nullptr, midh, midl, DMLP, EE, DMLP);
    gemm_tc<2><<<gFC2, thr, SMEM_GEMM>>>(midh, midl, w2h, w2l, fc2b, cov_in,
                                         out_cov, nullptr, nullptr, EE, DMLP, EE);

    // ---- tgt = targets + MLP(LN(functional_update)) ----
    ln_split<<<NTOK, thr>>>(fu_in, ln_im_g, ln_im_b, lnh, lnl);
    gemm_tc<1><<<gFC1, thr, SMEM_GEMM>>>(lnh, lnl, w1h, w1l, fc1b, nullptr,
                                         nullptr, midh, midl, DMLP, EE, DMLP);
    gemm_tc<2><<<gFC2, thr, SMEM_GEMM>>>(midh, midl, w2h, w2l, fc2b, tgt_in,
                                         out_tgt, tgh, tgl, EE, DMLP, EE);

    // ---- q = LN(cov) ----
    ln_split<<<NTOK, thr>>>(out_cov, ln_ia_g, ln_ia_b, qh, ql);

    // ---- ICL attention ----
    gemm_tc<0><<<gQK, thr, SMEM_GEMM>>>(qh, ql, iqkh, iqkl, nullptr, nullptr,
                                        qkv, nullptr, nullptr, 1024, EE, 1536);
    gemm_tc<0><<<gV, thr, SMEM_GEMM>>>(tgh, tgl, ivh, ivl, nullptr, nullptr,
                                       qkv + 1024, nullptr, nullptr, DAA, EE, 1536);
    rope_split<<<NTOK, thr>>>(qkv, fqh, fql, fkh, fkl, fvh, fvl);
    flash_mma<1><<<gFLASH, thr, SMEM_FLASH>>>(fqh, fql, fkh, fkl, fvh, fvl, aoh, aol);
    gemm_tc<3><<<gWO, thr, SMEM_GEMM>>>(aoh, aol, ioh, iol, nullptr, fu_in,
                                        out_fu, nullptr, nullptr, EE, DAA, EE);

    // ---- COV attention ----
    gemm_tc<0><<<gQKV, thr, SMEM_GEMM>>>(qh, ql, cqkvh, cqkvl, nullptr, nullptr,
                                         qkv, nullptr, nullptr, 1536, EE, 1536);
    rope_split<<<NTOK, thr>>>(qkv, fqh, fql, fkh, fkl, fvh, fvl);
    flash_mma<0><<<gFLASH, thr, SMEM_FLASH>>>(fqh, fql, fkh, fkl, fvh, fvl, aoh, aol);
    gemm_tc<3><<<gWO, thr, SMEM_GEMM>>>(aoh, aol, coh, col, nullptr, out_cov,
                                        out_cov, nullptr, nullptr, EE, DAA, EE);
}

// round 6
// speedup vs baseline: 3.6709x; 1.2323x over previous
#include <cuda_runtime.h>
#include <cuda_bf16.h>
#include <math.h>
#include <stdint.h>

#define BB 2
#define SS 2048
#define EE 1024
#define HH 8
#define DHH 64
#define DAA 512
#define DMLP 2048
#define NTOK 4096
#define SCALE_ATTN 0.04419417382415922f
#define SCALE_L2E 0.06375944628228341f   // SCALE_ATTN * log2(e)
#define LN_EPS 1e-5f

#define ROWB 80
#define PLANE_B 10240
#define STAGE_B 40960
#define SMEM_GEMM (2 * STAGE_B)

#define FROWB 144
#define FQPL 18432
#define FKPL 9216
#define FSTG 36864
#define SMEM_FLASH (2 * FQPL + 2 * FSTG)

// ---------------- scratch ----------------
__device__ float g_qkvI[NTOK * 1536];
__device__ float g_qkvC[NTOK * 1536];

__device__ uint16_t pLNh[NTOK * EE],     pLNl[NTOK * EE];
__device__ uint16_t pLN2h[NTOK * EE],    pLN2l[NTOK * EE];
__device__ uint16_t pMIDh[NTOK * DMLP],  pMIDl[NTOK * DMLP];
__device__ uint16_t pMID2h[NTOK * DMLP], pMID2l[NTOK * DMLP];
__device__ uint16_t pQh[NTOK * EE],      pQl[NTOK * EE];
__device__ uint16_t pTGTh[NTOK * EE],    pTGTl[NTOK * EE];
__device__ uint16_t pAOIh[NTOK * DAA],   pAOIl[NTOK * DAA];
__device__ uint16_t pAOCh[NTOK * DAA],   pAOCl[NTOK * DAA];
__device__ uint16_t pFQIh[NTOK * DAA],   pFQIl[NTOK * DAA];
__device__ uint16_t pFKIh[NTOK * DAA],   pFKIl[NTOK * DAA];
__device__ uint16_t pFVIh[NTOK * DAA],   pFVIl[NTOK * DAA];
__device__ uint16_t pFQCh[NTOK * DAA],   pFQCl[NTOK * DAA];
__device__ uint16_t pFKCh[NTOK * DAA],   pFKCl[NTOK * DAA];
__device__ uint16_t pFVCh[NTOK * DAA],   pFVCl[NTOK * DAA];

__device__ uint16_t pW1h[DMLP * EE],    pW1l[DMLP * EE];
__device__ uint16_t pW2h[EE * DMLP],    pW2l[EE * DMLP];
__device__ uint16_t pIQKh[1024 * EE],   pIQKl[1024 * EE];
__device__ uint16_t pIVh[DAA * EE],     pIVl[DAA * EE];
__device__ uint16_t pIOh[EE * DAA],     pIOl[EE * DAA];
__device__ uint16_t pCQKVh[1536 * EE],  pCQKVl[1536 * EE];
__device__ uint16_t pCOh[EE * DAA],     pCOl[EE * DAA];

// ---------------- helpers ----------------
__device__ __forceinline__ uint32_t pk2(__nv_bfloat16 a, __nv_bfloat16 b) {
    uint16_t ra = *reinterpret_cast<uint16_t*>(&a);
    uint16_t rb = *reinterpret_cast<uint16_t*>(&b);
    return (uint32_t)ra | ((uint32_t)rb << 16);
}
__device__ __forceinline__ void split1(float x, __nv_bfloat16& h, __nv_bfloat16& l) {
    h = __float2bfloat16(x);
    l = __float2bfloat16(x - __bfloat162float(h));
}
__device__ __forceinline__ void mma16816(float* c, const uint32_t* a, const uint32_t* b) {
    asm volatile(
        "mma.sync.aligned.m16n8k16.row.col.f32.bf16.bf16.f32 "
        "{%0,%1,%2,%3}, {%4,%5,%6,%7}, {%8,%9}, {%0,%1,%2,%3};"
        : "+f"(c[0]), "+f"(c[1]), "+f"(c[2]), "+f"(c[3])
        : "r"(a[0]), "r"(a[1]), "r"(a[2]), "r"(a[3]), "r"(b[0]), "r"(b[1]));
}
__device__ __forceinline__ void ldsm4(uint32_t& r0, uint32_t& r1, uint32_t& r2, uint32_t& r3,
                                      uint32_t addr) {
    asm volatile("ldmatrix.sync.aligned.m8n8.x4.shared.b16 {%0,%1,%2,%3}, [%4];"
                 : "=r"(r0), "=r"(r1), "=r"(r2), "=r"(r3) : "r"(addr));
}
__device__ __forceinline__ void ldsm4t(uint32_t& r0, uint32_t& r1, uint32_t& r2, uint32_t& r3,
                                       uint32_t addr) {
    asm volatile("ldmatrix.sync.aligned.m8n8.x4.trans.shared.b16 {%0,%1,%2,%3}, [%4];"
                 : "=r"(r0), "=r"(r1), "=r"(r2), "=r"(r3) : "r"(addr));
}
__device__ __forceinline__ void cpa16(uint32_t s, const void* g) {
    asm volatile("cp.async.ca.shared.global [%0], [%1], 16;" :: "r"(s), "l"(g));
}
__device__ __forceinline__ void cpa_commit() {
    asm volatile("cp.async.commit_group;" ::: "memory");
}
template<int N>
__device__ __forceinline__ void cpa_wait() {
    asm volatile("cp.async.wait_group %0;" :: "n"(N) : "memory");
}
__device__ __forceinline__ float exp2p(float x) {
    x = fmaxf(x, -80.f);
    float n = rintf(x);
    float f = x - n;
    float p = 1.3333558146428443e-3f;
    p = p * f + 9.618129107628477e-3f;
    p = p * f + 5.550410866482158e-2f;
    p = p * f + 2.402265069591007e-1f;
    p = p * f + 6.931471805599453e-1f;
    p = p * f + 1.0f;
    return p * __int_as_float(((int)n + 127) << 23);
}

__device__ __forceinline__ float block_reduce_sum(float v) {
    __shared__ float red[32];
    int lane = threadIdx.x & 31, w = threadIdx.x >> 5;
#pragma unroll
    for (int o = 16; o > 0; o >>= 1) v += __shfl_xor_sync(0xffffffffu, v, o);
    __syncthreads();
    if (lane == 0) red[w] = v;
    __syncthreads();
    v = (lane < 8) ? red[lane] : 0.f;
#pragma unroll
    for (int o = 16; o > 0; o >>= 1) v += __shfl_xor_sync(0xffffffffu, v, o);
    return v;
}

// ---------------- LayerNorm -> bf16 hi/lo planes ----------------
__global__ void ln_split(const float* __restrict__ x, const float* __restrict__ g,
                         const float* __restrict__ b,
                         uint16_t* __restrict__ oh, uint16_t* __restrict__ ol) {
    int row = blockIdx.x, t = threadIdx.x;
    float4 v = *(const float4*)&x[(size_t)row * EE + 4 * t];
    float s = v.x + v.y + v.z + v.w;
    float mean = block_reduce_sum(s) * (1.0f / EE);
    float d0 = v.x - mean, d1 = v.y - mean, d2 = v.z - mean, d3 = v.w - mean;
    float var = block_reduce_sum(d0 * d0 + d1 * d1 + d2 * d2 + d3 * d3) * (1.0f / EE);
    float rstd = rsqrtf(var + LN_EPS);
    float4 gg = *(const float4*)&g[4 * t];
    float4 bb = *(const float4*)&b[4 * t];
    float y0 = d0 * rstd * gg.x + bb.x;
    float y1 = d1 * rstd * gg.y + bb.y;
    float y2 = d2 * rstd * gg.z + bb.z;
    float y3 = d3 * rstd * gg.w + bb.w;
    __nv_bfloat16 h0, h1, h2, h3, l0, l1, l2, l3;
    split1(y0, h0, l0); split1(y1, h1, l1); split1(y2, h2, l2); split1(y3, h3, l3);
    size_t off = (size_t)row * EE + 4 * t;
    *(uint2*)&oh[off] = make_uint2(pk2(h0, h1), pk2(h2, h3));
    *(uint2*)&ol[off] = make_uint2(pk2(l0, l1), pk2(l2, l3));
}

// ---------------- weight conversion, single launch for all 10 matrices ----------------
__device__ __forceinline__ void convB_body(const float* __restrict__ W,
                                           uint16_t* __restrict__ Bh,
                                           uint16_t* __restrict__ Bl, int K, int N) {
    __shared__ float ts[64][129];
    int nt = blockIdx.x, kt = blockIdx.y, tid = threadIdx.x;
    int k0 = kt * 64, n0 = nt * 128;
#pragma unroll
    for (int i = 0; i < 32; i++) {
        int idx = tid + i * 256;
        int kk = idx >> 7, nn = idx & 127;
        ts[kk][nn] = W[(size_t)(k0 + kk) * N + n0 + nn];
    }
    __syncthreads();
#pragma unroll
    for (int j = 0; j < 4; j++) {
        int job = tid + j * 256;
        int n = job >> 3, kg = (job & 7) * 8;
        __nv_bfloat16 h[8], l[8];
#pragma unroll
        for (int i = 0; i < 8; i++) split1(ts[kg + i][n], h[i], l[i]);
        uint4 uh = make_uint4(pk2(h[0], h[1]), pk2(h[2], h[3]), pk2(h[4], h[5]), pk2(h[6], h[7]));
        uint4 ul = make_uint4(pk2(l[0], l[1]), pk2(l[2], l[3]), pk2(l[4], l[5]), pk2(l[6], l[7]));
        size_t off = (size_t)(n0 + n) * K + k0 + kg;
        *(uint4*)&Bh[off] = uh;
        *(uint4*)&Bl[off] = ul;
    }
}

struct ConvJobs {
    const float* src[10];
    uint16_t* dh[10];
    uint16_t* dl[10];
    int K[10], N[10];
};
__global__ void conv_all(ConvJobs j) {
    int w = blockIdx.z;
    int K = j.K[w], N = j.N[w];
    if (blockIdx.x * 128 >= N || blockIdx.y * 64 >= K) return;
    convB_body(j.src[w], j.dh[w], j.dl[w], K, N);
}

// ---------------- HMMA bf16-split GEMM ----------------
// MODE 0: C=AB(fp32, ldC)  1: planes=gelu(AB+bias)  2: C=AB+bias+R (+planes)  3: C=AB+R
template<int MODE>
__global__ void __launch_bounds__(256) gemm_tc(
    const uint16_t* __restrict__ Ah, const uint16_t* __restrict__ Al,
    const uint16_t* __restrict__ Bh, const uint16_t* __restrict__ Bl,
    const float* __restrict__ bias, const float* __restrict__ R,
    float* __restrict__ C, uint16_t* __restrict__ Ch, uint16_t* __restrict__ Cl,
    int N, int K, int ldC)
{
    extern __shared__ char sm[];
    const uint32_t sbase = (uint32_t)__cvta_generic_to_shared(sm);
    const int tid = threadIdx.x;
    const int warp = tid >> 5, lane = tid & 31;
    const int wm = warp & 1, wn = warp >> 1;
    const int m0 = blockIdx.y * 128, n0 = blockIdx.x * 128;
    const int KT = K >> 5;

    const uint16_t* gA[2] = { Ah + (size_t)m0 * K, Al + (size_t)m0 * K };
    const uint16_t* gB[2] = { Bh + (size_t)n0 * K, Bl + (size_t)n0 * K };

    const int rl = lane & 7, grp = lane >> 3;
    const int a_r = rl + (grp & 1) * 8;
    const int a_c = (grp >> 1) * 8;
    const int b_r = rl + ((grp >> 1) & 1) * 8;
    const int b_c = (grp & 1) * 8;

    float acc[4][4][4];
#pragma unroll
    for (int i = 0; i < 4; i++)
#pragma unroll
        for (int j = 0; j < 4; j++)
#pragma unroll
            for (int k = 0; k < 4; k++) acc[i][j][k] = 0.f;

    auto issue = [&](int stage, int kt) {
        uint32_t s0 = sbase + stage * STAGE_B;
        int kel = kt * 32;
#pragma unroll
        for (int pl = 0; pl < 4; pl++) {
            const uint16_t* g = (pl < 2) ? gA[pl] : gB[pl - 2];
#pragma unroll
            for (int i = 0; i < 2; i++) {
                int seg = tid + i * 256;
                int m = seg >> 2, s = seg & 3;
                cpa16(s0 + pl * PLANE_B + m * ROWB + s * 16,
                      g + (size_t)m * K + kel + s * 8);
            }
        }
        cpa_commit();
    };

    issue(0, 0);
    for (int kt = 0; kt < KT; kt++) {
        int st = kt & 1;
        if (kt + 1 < KT) { issue(st ^ 1, kt + 1); cpa_wait<1>(); }
        else             { cpa_wait<0>(); }
        __syncthreads();

        uint32_t sA_h = sbase + st * STAGE_B;
        uint32_t sA_l = sA_h + PLANE_B;
        uint32_t sB_h = sA_h + 2 * PLANE_B;
        uint32_t sB_l = sA_h + 3 * PLANE_B;

#pragma unroll
        for (int ks = 0; ks < 2; ks++) {
            const int kk = ks * 16;
            uint32_t bh[2][4], bl[2][4];
#pragma unroll
            for (int ntp = 0; ntp < 2; ntp++) {
                uint32_t off = (uint32_t)((wn * 32 + ntp * 16 + b_r) * ROWB + (kk + b_c) * 2);
                ldsm4(bh[ntp][0], bh[ntp][1], bh[ntp][2], bh[ntp][3], sB_h + off);
                ldsm4(bl[ntp][0], bl[ntp][1], bl[ntp][2], bl[ntp][3], sB_l + off);
            }
#pragma unroll
            for (int mt = 0; mt < 4; mt++) {
                uint32_t off = (uint32_t)((wm * 64 + mt * 16 + a_r) * ROWB + (kk + a_c) * 2);
                uint32_t ah[4], al[4];
                ldsm4(ah[0], ah[1], ah[2], ah[3], sA_h + off);
                ldsm4(al[0], al[1], al[2], al[3], sA_l + off);
#pragma unroll
                for (int nt = 0; nt < 4; nt++) {
                    uint32_t bfh[2] = { bh[nt >> 1][(nt & 1) * 2], bh[nt >> 1][(nt & 1) * 2 + 1] };
                    uint32_t bfl[2] = { bl[nt >> 1][(nt & 1) * 2], bl[nt >> 1][(nt & 1) * 2 + 1] };
                    mma16816(acc[mt][nt], ah, bfh);
                    mma16816(acc[mt][nt], ah, bfl);
                    mma16816(acc[mt][nt], al, bfh);
                }
            }
        }
        __syncthreads();
    }

    const int r = lane >> 2, q = lane & 3;
#pragma unroll
    for (int mt = 0; mt < 4; mt++) {
#pragma unroll
        for (int nt = 0; nt < 4; nt++) {
            int row = m0 + wm * 64 + mt * 16 + r;
            int col = n0 + wn * 32 + nt * 8 + q * 2;
#pragma unroll
            for (int half = 0; half < 2; half++) {
                int rr2 = row + half * 8;
                float v0 = acc[mt][nt][half * 2 + 0];
                float v1 = acc[mt][nt][half * 2 + 1];
                size_t gidx = (size_t)rr2 * ldC + col;
                if (MODE == 1) {
                    v0 += bias[col];
                    v1 += bias[col + 1];
                    v0 = 0.5f * v0 * (1.0f + erff(v0 * 0.70710678118654752f));
                    v1 = 0.5f * v1 * (1.0f + erff(v1 * 0.70710678118654752f));
                    __nv_bfloat16 h0, h1, l0, l1;
                    split1(v0, h0, l0); split1(v1, h1, l1);
                    *(uint32_t*)&Ch[gidx] = pk2(h0, h1);
                    *(uint32_t*)&Cl[gidx] = pk2(l0, l1);
                } else {
                    if (MODE == 2) {
                        float2 rv = *(const float2*)&R[gidx];
                        v0 += bias[col] + rv.x;
                        v1 += bias[col + 1] + rv.y;
                    } else if (MODE == 3) {
                        float2 rv = *(const float2*)&R[gidx];
                        v0 += rv.x;
                        v1 += rv.y;
                    }
                    *(float2*)&C[gidx] = make_float2(v0, v1);
                    if (MODE == 2 && Ch) {
                        __nv_bfloat16 h0, h1, l0, l1;
                        split1(v0, h0, l0); split1(v1, h1, l1);
                        *(uint32_t*)&Ch[gidx] = pk2(h0, h1);
                        *(uint32_t*)&Cl[gidx] = pk2(l0, l1);
                    }
                }
            }
        }
    }
}

// ---------------- RoPE + split to flash planes ----------------
__global__ void rope_split(const float* __restrict__ qkv,
                           uint16_t* __restrict__ fqh, uint16_t* __restrict__ fql,
                           uint16_t* __restrict__ fkh, uint16_t* __restrict__ fkl,
                           uint16_t* __restrict__ fvh, uint16_t* __restrict__ fvl) {
    int row = blockIdx.x, t = threadIdx.x;
    int i = t & 31;
    int s = row & (SS - 1);
    float inv = __expf(-logf(10000.0f) * ((float)i / 32.0f));
    float ang = (float)s * inv;
    float c = cosf(ang), sn = sinf(ang);
    const float* base = qkv + (size_t)row * 1536;
    size_t dst = (size_t)row * DAA + 2 * t;

    float x1 = base[2 * t], x2 = base[2 * t + 1];
    float o1 = x1 * c - x2 * sn, o2 = x1 * sn + x2 * c;
    __nv_bfloat16 h0, h1, l0, l1;
    split1(o1, h0, l0); split1(o2, h1, l1);
    *(uint32_t*)&fqh[dst] = pk2(h0, h1);
    *(uint32_t*)&fql[dst] = pk2(l0, l1);

    x1 = base[512 + 2 * t]; x2 = base[512 + 2 * t + 1];
    o1 = x1 * c - x2 * sn; o2 = x1 * sn + x2 * c;
    split1(o1, h0, l0); split1(o2, h1, l1);
    *(uint32_t*)&fkh[dst] = pk2(h0, h1);
    *(uint32_t*)&fkl[dst] = pk2(l0, l1);

    x1 = base[1024 + 2 * t]; x2 = base[1024 + 2 * t + 1];
    split1(x1, h0, l0); split1(x2, h1, l1);
    *(uint32_t*)&fvh[dst] = pk2(h0, h1);
    *(uint32_t*)&fvl[dst] = pk2(l0, l1);
}

// ---------------- Flash attention, HMMA + poly exp2 ----------------
template<int ICL>
__global__ void __launch_bounds__(256) flash_mma(
    const uint16_t* __restrict__ Qh, const uint16_t* __restrict__ Ql,
    const uint16_t* __restrict__ Kh, const uint16_t* __restrict__ Kl,
    const uint16_t* __restrict__ Vh, const uint16_t* __restrict__ Vl,
    uint16_t* __restrict__ Oh, uint16_t* __restrict__ Ol)
{
    extern __shared__ char sm[];
    const uint32_t sb = (uint32_t)__cvta_generic_to_shared(sm);
    const uint32_t sQh = sb, sQl = sb + FQPL;
    const uint32_t sKV = sb + 2 * FQPL;
    const int tid = threadIdx.x, warp = tid >> 5, lane = tid & 31;
    const int qt = gridDim.x - 1 - blockIdx.x;
    const int bh = blockIdx.y, b = bh >> 3, h = bh & 7;
    const int qg0 = qt * 128;
    const size_t tokb = (size_t)b * SS;
    const int rb = warp * 16;

    const int rl = lane & 7, grp = lane >> 3;
    const int a_r = rl + (grp & 1) * 8;
    const int a_c = (grp >> 1) * 8;
    const int b_r = rl + ((grp >> 1) & 1) * 8;
    const int b_c = (grp & 1) * 8;

#pragma unroll
    for (int i = 0; i < 8; i++) {
        int job = tid + i * 256;
        int pl = job >> 10, r = (job >> 3) & 127, s = job & 7;
        const uint16_t* g = (pl ? Ql : Qh) + (tokb + qg0 + r) * DAA + h * DHH + s * 8;
        cpa16((pl ? sQl : sQh) + r * FROWB + s * 16, g);
    }
    cpa_commit();

    float out[8][4];
#pragma unroll
    for (int i = 0; i < 8; i++)
#pragma unroll
        for (int j = 0; j < 4; j++) out[i][j] = 0.f;
    float mrow[2] = { -1e30f, -1e30f }, lrow[2] = { 0.f, 0.f };

    const int ktmax = (qg0 + 127) >> 6;

    auto issueKV = [&](int st, int kt) {
        uint32_t s0 = sKV + st * FSTG;
        int kg0 = kt * 64;
#pragma unroll
        for (int i = 0; i < 8; i++) {
            int job = tid + i * 256;
            int pl = job >> 9, r = (job >> 3) & 63, s = job & 7;
            const uint16_t* gp = (pl == 0) ? Kh : (pl == 1) ? Kl : (pl == 2) ? Vh : Vl;
            cpa16(s0 + pl * FKPL + r * FROWB + s * 16,
                  gp + (tokb + kg0 + r) * DAA + h * DHH + s * 8);
        }
        cpa_commit();
    };
    issueKV(0, 0);

    const int qrow0 = qg0 + rb + (lane >> 2);

    for (int kt = 0; kt <= ktmax; kt++) {
        int st = kt & 1;
        int kg0 = kt * 64;
        if (kt < ktmax) { issueKV(st ^ 1, kt + 1); cpa_wait<1>(); }
        else            { cpa_wait<0>(); }
        __syncthreads();

        uint32_t sK_h = sKV + st * FSTG;
        uint32_t sK_l = sK_h + FKPL;
        uint32_t sV_h = sK_h + 2 * FKPL;
        uint32_t sV_l = sK_h + 3 * FKPL;

        float sc[8][4];
#pragma unroll
        for (int i = 0; i < 8; i++)
#pragma unroll
            for (int j = 0; j < 4; j++) sc[i][j] = 0.f;
#pragma unroll
        for (int k16 = 0; k16 < 4; k16++) {
            uint32_t qoff = (uint32_t)((rb + a_r) * FROWB + (k16 * 16 + a_c) * 2);
            uint32_t ah[4], al[4];
            ldsm4(ah[0], ah[1], ah[2], ah[3], sQh + qoff);
            ldsm4(al[0], al[1], al[2], al[3], sQl + qoff);
#pragma unroll
            for (int ntp = 0; ntp < 4; ntp++) {
                uint32_t koff = (uint32_t)((ntp * 16 + b_r) * FROWB + (k16 * 16 + b_c) * 2);
                uint32_t kh[4], kl[4];
                ldsm4(kh[0], kh[1], kh[2], kh[3], sK_h + koff);
                ldsm4(kl[0], kl[1], kl[2], kl[3], sK_l + koff);
#pragma unroll
                for (int u = 0; u < 2; u++) {
                    int nt = ntp * 2 + u;
                    uint32_t bfh[2] = { kh[u * 2], kh[u * 2 + 1] };
                    uint32_t bfl[2] = { kl[u * 2], kl[u * 2 + 1] };
                    mma16816(sc[nt], ah, bfh);
                    mma16816(sc[nt], ah, bfl);
                    mma16816(sc[nt], al, bfh);
                }
            }
        }

        const bool boundary = (kg0 + 63 >= qg0);
#pragma unroll
        for (int nt = 0; nt < 8; nt++) {
#pragma unroll
            for (int c = 0; c < 4; c++) {
                float v = sc[nt][c] * SCALE_L2E;
                if (boundary) {
                    int qg = qrow0 + (c >> 1) * 8;
                    int kg = kg0 + nt * 8 + (lane & 3) * 2 + (c & 1);
                    bool allow = ICL ? (kg < qg || (qg | kg) == 0) : (kg <= qg);
                    v = allow ? v : -1e30f;
                }
                sc[nt][c] = v;
            }
        }

#pragma unroll
        for (int ri = 0; ri < 2; ri++) {
            float mx = -1e30f;
#pragma unroll
            for (int nt = 0; nt < 8; nt++)
                mx = fmaxf(mx, fmaxf(sc[nt][ri * 2], sc[nt][ri * 2 + 1]));
            mx = fmaxf(mx, __shfl_xor_sync(0xffffffffu, mx, 1));
            mx = fmaxf(mx, __shfl_xor_sync(0xffffffffu, mx, 2));
            float mn = fmaxf(mrow[ri], mx);
            float corr = exp2p(mrow[ri] - mn);
            mrow[ri] = mn;
            float rs = 0.f;
#pragma unroll
            for (int nt = 0; nt < 8; nt++) {
                float p0 = exp2p(sc[nt][ri * 2] - mn);
                float p1 = exp2p(sc[nt][ri * 2 + 1] - mn);
                sc[nt][ri * 2] = p0;
                sc[nt][ri * 2 + 1] = p1;
                rs += p0 + p1;
            }
            rs += __shfl_xor_sync(0xffffffffu, rs, 1);
            rs += __shfl_xor_sync(0xffffffffu, rs, 2);
            lrow[ri] = lrow[ri] * corr + rs;
#pragma unroll
            for (int nt = 0; nt < 8; nt++) {
                out[nt][ri * 2] *= corr;
                out[nt][ri * 2 + 1] *= corr;
            }
        }

#pragma unroll
        for (int j = 0; j < 4; j++) {
            uint32_t aP[4];
            aP[0] = pk2(__float2bfloat16(sc[2 * j][0]),     __float2bfloat16(sc[2 * j][1]));
            aP[1] = pk2(__float2bfloat16(sc[2 * j][2]),     __float2bfloat16(sc[2 * j][3]));
            aP[2] = pk2(__float2bfloat16(sc[2 * j + 1][0]), __float2bfloat16(sc[2 * j + 1][1]));
            aP[3] = pk2(__float2bfloat16(sc[2 * j + 1][2]), __float2bfloat16(sc[2 * j + 1][3]));
#pragma unroll
            for (int nt2 = 0; nt2 < 4; nt2++) {
                uint32_t voff = (uint32_t)((j * 16 + (grp & 1) * 8 + rl) * FROWB
                                           + (nt2 * 16 + (grp >> 1) * 8) * 2);
                uint32_t bv[4];
                ldsm4t(bv[0], bv[1], bv[2], bv[3], sV_h + voff);
                {
                    uint32_t b0[2] = { bv[0], bv[1] }, b1[2] = { bv[2], bv[3] };
                    mma16816(out[nt2 * 2], aP, b0);
                    mma16816(out[nt2 * 2 + 1], aP, b1);
                }
                ldsm4t(bv[0], bv[1], bv[2], bv[3], sV_l + voff);
                {
                    uint32_t b0[2] = { bv[0], bv[1] }, b1[2] = { bv[2], bv[3] };
                    mma16816(out[nt2 * 2], aP, b0);
                    mma16816(out[nt2 * 2 + 1], aP, b1);
                }
            }
        }
        __syncthreads();
    }

#pragma unroll
    for (int ri = 0; ri < 2; ri++) {
        float inv = 1.0f / lrow[ri];
        size_t rbase = (tokb + qrow0 + ri * 8) * DAA + h * DHH + (lane & 3) * 2;
#pragma unroll
        for (int nt = 0; nt < 8; nt++) {
            float v0 = out[nt][ri * 2] * inv;
            float v1 = out[nt][ri * 2 + 1] * inv;
            __nv_bfloat16 h0, h1, l0, l1;
            split1(v0, h0, l0); split1(v1, h1, l1);
            *(uint32_t*)&Oh[rbase + nt * 8] = pk2(h0, h1);
            *(uint32_t*)&Ol[rbase + nt * 8] = pk2(l0, l1);
        }
    }
}

// ---------------- host driver ----------------
#define GETSYM(T, var, sym) T* var; { void* _p; cudaGetSymbolAddress(&_p, sym); var = (T*)_p; }

extern "C" void kernel_launch(void* const* d_in, const int* in_sizes, int n_in,
                              void* d_out, int out_size)
{
    const float* cov_in  = (const float*)d_in[0];
    const float* tgt_in  = (const float*)d_in[1];
    const float* fu_in   = (const float*)d_in[2];
    const float* fc1w    = (const float*)d_in[3];
    const float* fc1b    = (const float*)d_in[4];
    const float* fc2w    = (const float*)d_in[5];
    const float* fc2b    = (const float*)d_in[6];
    const float* icl_wq  = (const float*)d_in[7];
    const float* icl_wk  = (const float*)d_in[8];
    const float* icl_wv  = (const float*)d_in[9];
    const float* icl_wo  = (const float*)d_in[10];
    const float* cov_wq  = (const float*)d_in[11];
    const float* cov_wk  = (const float*)d_in[12];
    const float* cov_wv  = (const float*)d_in[13];
    const float* cov_wo  = (const float*)d_in[14];
    const float* ln_cm_g = (const float*)d_in[15];
    const float* ln_cm_b = (const float*)d_in[16];
    const float* ln_ia_g = (const float*)d_in[17];
    const float* ln_ia_b = (const float*)d_in[18];
    const float* ln_im_g = (const float*)d_in[19];
    const float* ln_im_b = (const float*)d_in[20];

    float* out_cov = (float*)d_out;
    float* out_tgt = out_cov + (size_t)NTOK * EE;
    float* out_fu  = out_tgt + (size_t)NTOK * EE;

    GETSYM(float, qkvI, g_qkvI)    GETSYM(float, qkvC, g_qkvC)
    GETSYM(uint16_t, lnh, pLNh)    GETSYM(uint16_t, lnl, pLNl)
    GETSYM(uint16_t, ln2h, pLN2h)  GETSYM(uint16_t, ln2l, pLN2l)
    GETSYM(uint16_t, midh, pMIDh)  GETSYM(uint16_t, midl, pMIDl)
    GETSYM(uint16_t, mid2h, pMID2h) GETSYM(uint16_t, mid2l, pMID2l)
    GETSYM(uint16_t, qh, pQh)      GETSYM(uint16_t, ql, pQl)
    GETSYM(uint16_t, tgh, pTGTh)   GETSYM(uint16_t, tgl, pTGTl)
    GETSYM(uint16_t, aoIh, pAOIh)  GETSYM(uint16_t, aoIl, pAOIl)
    GETSYM(uint16_t, aoCh, pAOCh)  GETSYM(uint16_t, aoCl, pAOCl)
    GETSYM(uint16_t, fqIh, pFQIh)  GETSYM(uint16_t, fqIl, pFQIl)
    GETSYM(uint16_t, fkIh, pFKIh)  GETSYM(uint16_t, fkIl, pFKIl)
    GETSYM(uint16_t, fvIh, pFVIh)  GETSYM(uint16_t, fvIl, pFVIl)
    GETSYM(uint16_t, fqCh, pFQCh)  GETSYM(uint16_t, fqCl, pFQCl)
    GETSYM(uint16_t, fkCh, pFKCh)  GETSYM(uint16_t, fkCl, pFKCl)
    GETSYM(uint16_t, fvCh, pFVCh)  GETSYM(uint16_t, fvCl, pFVCl)
    GETSYM(uint16_t, w1h, pW1h)    GETSYM(uint16_t, w1l, pW1l)
    GETSYM(uint16_t, w2h, pW2h)    GETSYM(uint16_t, w2l, pW2l)
    GETSYM(uint16_t, iqkh, pIQKh)  GETSYM(uint16_t, iqkl, pIQKl)
    GETSYM(uint16_t, ivh, pIVh)    GETSYM(uint16_t, ivl, pIVl)
    GETSYM(uint16_t, ioh, pIOh)    GETSYM(uint16_t, iol, pIOl)
    GETSYM(uint16_t, cqkvh, pCQKVh) GETSYM(uint16_t, cqkvl, pCQKVl)
    GETSYM(uint16_t, coh, pCOh)    GETSYM(uint16_t, col, pCOl)

    static cudaStream_t s2 = nullptr;
    static cudaEvent_t ev0 = nullptr, evq = nullptr, evend = nullptr;
    if (!s2) {
        cudaStreamCreateWithFlags(&s2, cudaStreamNonBlocking);
        cudaEventCreateWithFlags(&ev0, cudaEventDisableTiming);
        cudaEventCreateWithFlags(&evq, cudaEventDisableTiming);
        cudaEventCreateWithFlags(&evend, cudaEventDisableTiming);
        cudaFuncSetAttribute(gemm_tc<0>, cudaFuncAttributeMaxDynamicSharedMemorySize, SMEM_GEMM);
        cudaFuncSetAttribute(gemm_tc<1>, cudaFuncAttributeMaxDynamicSharedMemorySize, SMEM_GEMM);
        cudaFuncSetAttribute(gemm_tc<2>, cudaFuncAttributeMaxDynamicSharedMemorySize, SMEM_GEMM);
        cudaFuncSetAttribute(gemm_tc<3>, cudaFuncAttributeMaxDynamicSharedMemorySize, SMEM_GEMM);
        cudaFuncSetAttribute(flash_mma<0>, cudaFuncAttributeMaxDynamicSharedMemorySize, SMEM_FLASH);
        cudaFuncSetAttribute(flash_mma<1>, cudaFuncAttributeMaxDynamicSharedMemorySize, SMEM_FLASH);
    }

    const dim3 thr(256);
    const dim3 gFC1(DMLP / 128, NTOK / 128);
    const dim3 gFC2(EE / 128, NTOK / 128);
    const dim3 gQK(8, NTOK / 128);
    const dim3 gV(4, NTOK / 128);
    const dim3 gQKV(12, NTOK / 128);
    const dim3 gWO(EE / 128, NTOK / 128);
    const dim3 gFLASH(SS / 128, BB * HH);

    // ---- all weight conversions, one launch (legacy stream) ----
    ConvJobs cj;
    cj.src[0] = fc1w;   cj.dh[0] = w1h;              cj.dl[0] = w1l;              cj.K[0] = EE;   cj.N[0] = DMLP;
    cj.src[1] = fc2w;   cj.dh[1] = w2h;              cj.dl[1] = w2l;              cj.K[1] = DMLP; cj.N[1] = EE;
    cj.src[2] = icl_wq; cj.dh[2] = iqkh;             cj.dl[2] = iqkl;             cj.K[2] = EE;   cj.N[2] = DAA;
    cj.src[3] = icl_wk; cj.dh[3] = iqkh + 512 * EE;  cj.dl[3] = iqkl + 512 * EE;  cj.K[3] = EE;   cj.N[3] = DAA;
    cj.src[4] = icl_wv; cj.dh[4] = ivh;              cj.dl[4] = ivl;              cj.K[4] = EE;   cj.N[4] = DAA;
    cj.src[5] = cov_wq; cj.dh[5] = cqkvh;            cj.dl[5] = cqkvl;            cj.K[5] = EE;   cj.N[5] = DAA;
    cj.src[6] = cov_wk; cj.dh[6] = cqkvh + 512 * EE; cj.dl[6] = cqkvl + 512 * EE; cj.K[6] = EE;   cj.N[6] = DAA;
    cj.src[7] = cov_wv; cj.dh[7] = cqkvh + 1024 * EE;cj.dl[7] = cqkvl + 1024 * EE;cj.K[7] = EE;   cj.N[7] = DAA;
    cj.src[8] = icl_wo; cj.dh[8] = ioh;              cj.dl[8] = iol;              cj.K[8] = DAA;  cj.N[8] = EE;
    cj.src[9] = cov_wo; cj.dh[9] = coh;              cj.dl[9] = col;              cj.K[9] = DAA;  cj.N[9] = EE;
    conv_all<<<dim3(16, 32, 10), thr>>>(cj);
    cudaEventRecord(ev0, 0);
    cudaStreamWaitEvent(s2, ev0, 0);

    // ---- chain2 on s2: tgt = targets + MLP(LN(functional_update)) ----
    ln_split<<<NTOK, thr, 0, s2>>>(fu_in, ln_im_g, ln_im_b, ln2h, ln2l);
    gemm_tc<1><<<gFC1, thr, SMEM_GEMM, s2>>>(ln2h, ln2l, w1h, w1l, fc1b, nullptr,
                                             nullptr, mid2h, mid2l, DMLP, EE, DMLP);
    gemm_tc<2><<<gFC2, thr, SMEM_GEMM, s2>>>(mid2h, mid2l, w2h, w2l, fc2b, tgt_in,
                                             out_tgt, tgh, tgl, EE, DMLP, EE);

    // ---- chain1 on legacy: cov = covariates + MLP(LN(covariates)); q = LN(cov) ----
    ln_split<<<NTOK, thr>>>(cov_in, ln_cm_g, ln_cm_b, lnh, lnl);
    gemm_tc<1><<<gFC1, thr, SMEM_GEMM>>>(lnh, lnl, w1h, w1l, fc1b, nullptr,
                                         nullptr, midh, midl, DMLP, EE, DMLP);
    gemm_tc<2><<<gFC2, thr, SMEM_GEMM>>>(midh, midl, w2h, w2l, fc2b, cov_in,
                                         out_cov, nullptr, nullptr, EE, DMLP, EE);
    ln_split<<<NTOK, thr>>>(out_cov, ln_ia_g, ln_ia_b, qh, ql);
    cudaEventRecord(evq, 0);

    // ---- ICL attention on s2 (needs q + tgt) ----
    cudaStreamWaitEvent(s2, evq, 0);
    gemm_tc<0><<<gQK, thr, SMEM_GEMM, s2>>>(qh, ql, iqkh, iqkl, nullptr, nullptr,
                                            qkvI, nullptr, nullptr, 1024, EE, 1536);
    gemm_tc<0><<<gV, thr, SMEM_GEMM, s2>>>(tgh, tgl, ivh, ivl, nullptr, nullptr,
                                           qkvI + 1024, nullptr, nullptr, DAA, EE, 1536);
    rope_split<<<NTOK, thr, 0, s2>>>(qkvI, fqIh, fqIl, fkIh, fkIl, fvIh, fvIl);
    flash_mma<1><<<gFLASH, thr, SMEM_FLASH, s2>>>(fqIh, fqIl, fkIh, fkIl, fvIh, fvIl, aoIh, aoIl);
    gemm_tc<3><<<gWO, thr, SMEM_GEMM, s2>>>(aoIh, aoIl, ioh, iol, nullptr, fu_in,
                                            out_fu, nullptr, nullptr, EE, DAA, EE);
    cudaEventRecord(evend, s2);

    // ---- COV attention on legacy (needs only q) ----
    gemm_tc<0><<<gQKV, thr, SMEM_GEMM>>>(qh, ql, cqkvh, cqkvl, nullptr, nullptr,
                                         qkvC, nullptr, nullptr, 1536, EE, 1536);
    rope_split<<<NTOK, thr>>>(qkvC, fqCh, fqCl, fkCh, fkCl, fvCh, fvCl);
    flash_mma<0><<<gFLASH, thr, SMEM_FLASH>>>(fqCh, fqCl, fkCh, fkCl, fvCh, fvCl, aoCh, aoCl);
    gemm_tc<3><<<gWO, thr, SMEM_GEMM>>>(aoCh, aoCl, coh, col, nullptr, out_cov,
                                        out_cov, nullptr, nullptr, EE, DAA, EE);

    // join
    cudaStreamWaitEvent(0, evend, 0);
}